// round 9
// baseline (speedup 1.0000x reference)
#include <cuda_runtime.h>
#include <math.h>
#include <stdint.h>

#define S_LEN 8192
#define LCC   16
#define DW    256
#define DC    64
#define HC    128
#define HH    512
#define T_TAGS 64
#define H2    256
#define KIN   384      /* HC + DW */
#define NBC   8        /* CTAs per direction (one portable cluster) */
#define RT2   512

/* ------------------- scratch (device globals; no allocation) ------------- */
__device__ float g_Xc[(size_t)LCC * S_LEN * 4 * HC];
__device__ int   g_charidx[LCC * S_LEN];
__device__ float g_gates[S_LEN * 4 * HC];
__device__ float g_Hc[S_LEN * HC];
__device__ float g_Cc[S_LEN * HC];
__device__ float g_charfeat[S_LEN * HC];
__device__ float g_embeds[S_LEN * KIN];
__device__ float g_Gf[(size_t)S_LEN * 4 * H2];
__device__ float g_Gb[(size_t)S_LEN * 4 * H2];
__device__ float g_lstm_out[S_LEN * HH];
__device__ float g_logits[S_LEN * T_TAGS];

__device__ __forceinline__ float sigf(float x) { return 1.0f / (1.0f + expf(-x)); }

/* ---- PTX helpers ---- */
__device__ __forceinline__ uint32_t smem_u32(const void* p) {
    uint32_t a;
    asm("{ .reg .u64 t; cvta.to.shared.u64 t, %1; cvt.u32.u64 %0, t; }" : "=r"(a) : "l"(p));
    return a;
}
__device__ __forceinline__ uint32_t mapa_rank(uint32_t addr, uint32_t rank) {
    uint32_t r;
    asm("mapa.shared::cluster.u32 %0, %1, %2;" : "=r"(r) : "r"(addr), "r"(rank));
    return r;
}
__device__ __forceinline__ void mbar_wait_acq(uint32_t mbar, uint32_t parity) {
    uint32_t done;
    asm volatile(
        "{\n\t.reg .pred p;\n\t"
        "mbarrier.try_wait.parity.acquire.cluster.shared::cta.b64 p, [%1], %2;\n\t"
        "selp.b32 %0, 1, 0, p;\n\t}"
        : "=r"(done) : "r"(mbar), "r"(parity) : "memory");
    while (!done) {
        asm volatile(
            "{\n\t.reg .pred p;\n\t"
            "mbarrier.try_wait.parity.acquire.cluster.shared::cta.b64 p, [%1], %2, 0x989680;\n\t"
            "selp.b32 %0, 1, 0, p;\n\t}"
            : "=r"(done) : "r"(mbar), "r"(parity) : "memory");
    }
}
#define FMA2(acc, a, b) asm("fma.rn.f32x2 %0, %1, %2, %0;" : "+l"(acc) : "l"(a), "l"(b))
#define UNPACK2(lo, hi, v) asm("mov.b64 {%0,%1}, %2;" : "=f"(lo), "=f"(hi) : "l"(v))

/* ------------------- init: must run every launch (graph determinism) ----- */
__global__ void init_state() {
    int idx = blockIdx.x * blockDim.x + threadIdx.x;
    int stride = gridDim.x * blockDim.x;
    for (int i = idx; i < S_LEN * HC; i += stride) {
        g_Hc[i] = 0.0f;
        g_Cc[i] = 0.0f;
    }
}

__global__ void build_charidx(const int* __restrict__ charsets) {
    int idx = blockIdx.x * blockDim.x + threadIdx.x;
    if (idx >= LCC * S_LEN) return;
    int t = idx / S_LEN;
    int w = idx - t * S_LEN;
    g_charidx[idx] = charsets[w * LCC + t];
}

/* ------------------- generic fp32 GEMM ------------------------------------ */
__global__ void __launch_bounds__(256) gemm_tn(
    const float* __restrict__ A, int lda,
    const float* __restrict__ B,
    const float* __restrict__ bias,
    float* __restrict__ C, int M, int N, int K,
    const int* __restrict__ gidx, int rev)
{
    __shared__ float4 As4[16 * 16];
    __shared__ float4 Bs4[16 * 16];
    float* As = (float*)As4;
    float* Bs = (float*)Bs4;

    int tid = threadIdx.x;
    int m0 = blockIdx.y * 64, n0 = blockIdx.x * 64;
    int lm = tid >> 2;
    int kq = tid & 3;

    int mg = m0 + lm;
    int arow = gidx ? gidx[mg] : (rev ? (M - 1 - mg) : mg);
    const float* Ap = A + (size_t)arow * lda;
    const float* Bp = B + (size_t)(n0 + lm) * K;

    int ty = tid >> 4, tx = tid & 15;
    float acc[4][4];
#pragma unroll
    for (int i = 0; i < 4; i++)
#pragma unroll
        for (int j = 0; j < 4; j++) acc[i][j] = 0.0f;

    for (int k0 = 0; k0 < K; k0 += 16) {
        float4 a = *(const float4*)(Ap + k0 + kq * 4);
        float4 b = *(const float4*)(Bp + k0 + kq * 4);
        __syncthreads();
        As[(kq * 4 + 0) * 64 + lm] = a.x;
        As[(kq * 4 + 1) * 64 + lm] = a.y;
        As[(kq * 4 + 2) * 64 + lm] = a.z;
        As[(kq * 4 + 3) * 64 + lm] = a.w;
        Bs[(kq * 4 + 0) * 64 + lm] = b.x;
        Bs[(kq * 4 + 1) * 64 + lm] = b.y;
        Bs[(kq * 4 + 2) * 64 + lm] = b.z;
        Bs[(kq * 4 + 3) * 64 + lm] = b.w;
        __syncthreads();
#pragma unroll
        for (int kk = 0; kk < 16; kk++) {
            float4 av = As4[kk * 16 + ty];
            float4 bv = Bs4[kk * 16 + tx];
            acc[0][0] += av.x * bv.x; acc[0][1] += av.x * bv.y;
            acc[0][2] += av.x * bv.z; acc[0][3] += av.x * bv.w;
            acc[1][0] += av.y * bv.x; acc[1][1] += av.y * bv.y;
            acc[1][2] += av.y * bv.z; acc[1][3] += av.y * bv.w;
            acc[2][0] += av.z * bv.x; acc[2][1] += av.z * bv.y;
            acc[2][2] += av.z * bv.z; acc[2][3] += av.z * bv.w;
            acc[3][0] += av.w * bv.x; acc[3][1] += av.w * bv.y;
            acc[3][2] += av.w * bv.z; acc[3][3] += av.w * bv.w;
        }
    }
#pragma unroll
    for (int i = 0; i < 4; i++) {
        int m = m0 + ty * 4 + i;
        int n = n0 + tx * 4;
        float4 o;
        o.x = acc[i][0]; o.y = acc[i][1]; o.z = acc[i][2]; o.w = acc[i][3];
        if (bias) {
            o.x += bias[n + 0]; o.y += bias[n + 1];
            o.z += bias[n + 2]; o.w += bias[n + 3];
        }
        *(float4*)(C + (size_t)m * N + n) = o;
    }
}

/* ------------------- char LSTM pointwise update --------------------------- */
__global__ void char_update(const int* __restrict__ lengths, int t) {
    int idx = blockIdx.x * blockDim.x + threadIdx.x;
    if (idx >= S_LEN * HC) return;
    int w = idx / HC, u = idx - w * HC;
    const float* xrow = g_Xc + ((size_t)t * S_LEN + w) * (4 * HC);
    const float* grow = g_gates + (size_t)w * (4 * HC);
    float gi = grow[0 * HC + u] + xrow[0 * HC + u];
    float gf = grow[1 * HC + u] + xrow[1 * HC + u];
    float gg = grow[2 * HC + u] + xrow[2 * HC + u];
    float go = grow[3 * HC + u] + xrow[3 * HC + u];
    float c = g_Cc[idx];
    c = sigf(gf) * c + sigf(gi) * tanhf(gg);
    float h = sigf(go) * tanhf(c);
    g_Cc[idx] = c;
    g_Hc[idx] = h;
    if (t == lengths[w] - 1) g_charfeat[idx] = h;
}

/* ------------------- embeds = [charfeat | word_emb[sentence]] ------------- */
__global__ void build_embeds(const int* __restrict__ sentence,
                             const float* __restrict__ word_emb) {
    int idx = blockIdx.x * blockDim.x + threadIdx.x;
    if (idx >= S_LEN * KIN) return;
    int w = idx / KIN, j = idx - w * KIN;
    float v;
    if (j < HC) v = g_charfeat[w * HC + j];
    else        v = word_emb[(size_t)sentence[w] * DW + (j - HC)];
    g_embeds[idx] = v;
}

/* ------------------- cluster recurrence, two-phase step -------------------
 * 2 clusters of 8 CTAs (one per direction), 512 threads each.
 * Phase A (16 dot warps): wait wave t-1 -> 32 FMA2 dot -> 2 xor shfls ->
 *   seg0 lanes STS gate sums to s_gates[unit*4+gate] -> __syncthreads.
 * Phase B (warp 0 only): lane u = unit u: LDS.128 the 4 gates, accurate
 *   sigmoid/tanh gate math (10 MUFU total/CTA/step vs 160 before), STG
 *   lstm_out (coalesced), stage h, then lanes 0..31 push the 16 h-pairs to
 *   8 peers (4 plain st.shared::cluster.b64 each) + ONE
 *   mbarrier.arrive.release.cluster per lane (4 per src->dst pair).
 * Sync: 2 alternating COUNTING mbarriers (count=32, no expect_tx, no
 *   re-arm). Release-arrive orders the lane's DSMEM stores; consumers
 *   try_wait.parity.acquire.cluster. h double-buffered by step parity.   */
__global__ void __launch_bounds__(RT2, 1) __cluster_dims__(NBC, 1, 1)
recurrent_cluster(const float* __restrict__ WhhF, const float* __restrict__ WhhB)
{
    __shared__ __align__(16) float s_h[2][H2];
    __shared__ __align__(16) float s_gates[128];
    __shared__ __align__(16) float s_hl[32];
    __shared__ __align__(8) unsigned long long s_mbar[2];

    int tid = threadIdx.x;
    int wid = tid >> 5;
    int lane = tid & 31;
    int d = blockIdx.x >> 3;
    int b = blockIdx.x & 7;
    const float* Whh = d ? WhhB : WhhF;
    const float* G = d ? g_Gb : g_Gf;

    int seg = lane & 3;            /* k-split 0..3                 */
    int r_l = lane >> 2;           /* 0..7: j = r_l>>2, gk = r_l&3 */
    int j = r_l >> 2;
    int gk = r_l & 3;
    int u = b * 32 + wid * 2 + j;  /* global h-unit of this lane   */
    int row = gk * H2 + u;         /* gate row                     */

    /* 64 weights per thread, packed f32x2 */
    ulonglong2 w[16];
    const float* wrow = Whh + (size_t)row * H2;
#pragma unroll
    for (int jj = 0; jj < 16; jj++)
        w[jj] = *reinterpret_cast<const ulonglong2*>(wrow + (jj * 4 + seg) * 4);

    if (tid < H2) { s_h[0][tid] = 0.0f; s_h[1][tid] = 0.0f; }

    uint32_t mb0 = smem_u32(&s_mbar[0]);
    uint32_t mb1 = smem_u32(&s_mbar[1]);
    if (tid == 0) {
        asm volatile("mbarrier.init.shared.b64 [%0], %1;" :: "r"(mb0), "r"(32) : "memory");
        asm volatile("mbarrier.init.shared.b64 [%0], %1;" :: "r"(mb1), "r"(32) : "memory");
        asm volatile("fence.mbarrier_init.release.cluster;" ::: "memory");
    }

    /* warp0 per-lane push targets: peer = lane>>2, quarter = lane&3 */
    int peer = lane >> 2;
    int q = lane & 3;
    uint32_t rh[2], rmb[2];
    if (wid == 0) {
        rh[0] = mapa_rank(smem_u32(&s_h[0][0]), (uint32_t)peer);
        rh[1] = mapa_rank(smem_u32(&s_h[1][0]), (uint32_t)peer);
        rmb[0] = mapa_rank(mb0, (uint32_t)peer);
        rmb[1] = mapa_rank(mb1, (uint32_t)peer);
    }

    __syncthreads();
    asm volatile("barrier.cluster.arrive.aligned;" ::: "memory");
    asm volatile("barrier.cluster.wait.aligned;" ::: "memory");

    uint32_t ph0 = 0, ph1 = 0;
    float c = 0.0f;
    float gin = 0.0f;
    if (seg == 0) gin = G[row];    /* prefetch t=0 */

    for (int t = 0; t < S_LEN; t++) {
        int idx = t & 1;
        if (t > 0) {
            int wv = t - 1;                     /* wait wave t-1 */
            if ((wv & 1) == 0) { mbar_wait_acq(mb0, ph0); ph0 ^= 1; }
            else               { mbar_wait_acq(mb1, ph1); ph1 ^= 1; }
        }

        const float* hb = s_h[idx];
        unsigned long long acc0 = 0ull, acc1 = 0ull;
#pragma unroll
        for (int jj = 0; jj < 16; jj++) {
            ulonglong2 hv = *reinterpret_cast<const ulonglong2*>(hb + (jj * 4 + seg) * 4);
            FMA2(acc0, w[jj].x, hv.x);
            FMA2(acc1, w[jj].y, hv.y);
        }
        float a0, a1, a2, a3;
        UNPACK2(a0, a1, acc0);
        UNPACK2(a2, a3, acc1);
        float acc = (a0 + a1) + (a2 + a3);
        acc += __shfl_xor_sync(0xffffffffu, acc, 1);
        acc += __shfl_xor_sync(0xffffffffu, acc, 2);
        if (seg == 0) {
            s_gates[(wid * 2 + j) * 4 + gk] = acc + gin;
            if (t + 1 < S_LEN)
                gin = G[(size_t)(t + 1) * (4 * H2) + row];  /* prefetch next */
        }
        __syncthreads();

        if (wid == 0) {
            float4 g4 = *reinterpret_cast<const float4*>(&s_gates[lane * 4]);
            c = sigf(g4.y) * c + sigf(g4.x) * tanhf(g4.z);
            float h = sigf(g4.w) * tanhf(c);
            int outrow = d ? (S_LEN - 1 - t) : t;
            g_lstm_out[(size_t)outrow * HH + d * H2 + b * 32 + lane] = h;

            if (t + 1 < S_LEN) {
                s_hl[lane] = h;
                __syncwarp();
                uint32_t rbase = rh[idx ^ 1];   /* peer buf (t+1)&1 */
#pragma unroll
                for (int m = 0; m < 4; m++) {
                    int k = q + 4 * m;          /* pair index 0..15 */
                    unsigned long long pv =
                        *reinterpret_cast<const unsigned long long*>(&s_hl[2 * k]);
                    uint32_t ra = rbase + (uint32_t)(b * 32 + 2 * k) * 4u;
                    asm volatile("st.shared::cluster.b64 [%0], %1;"
                                 :: "r"(ra), "l"(pv) : "memory");
                }
                /* wave t signals on mbar[t&1]; release orders stores above */
                asm volatile(
                    "mbarrier.arrive.release.cluster.shared::cluster.b64 _, [%0];"
                    :: "r"(rmb[idx]) : "memory");
            }
        }
    }

    asm volatile("barrier.cluster.arrive.aligned;" ::: "memory");
    asm volatile("barrier.cluster.wait.aligned;" ::: "memory");
}

/* ------------------- log_softmax over 64 tags (one warp per word) --------- */
__global__ void logsoftmax_kernel(float* __restrict__ out) {
    int gt = blockIdx.x * blockDim.x + threadIdx.x;
    int warp = gt >> 5;
    int lane = gt & 31;
    if (warp >= S_LEN) return;
    const float* l = g_logits + (size_t)warp * T_TAGS;
    float a = l[lane], b = l[lane + 32];
    float m = fmaxf(a, b);
#pragma unroll
    for (int o = 16; o > 0; o >>= 1) m = fmaxf(m, __shfl_xor_sync(0xffffffffu, m, o));
    float s = expf(a - m) + expf(b - m);
#pragma unroll
    for (int o = 16; o > 0; o >>= 1) s += __shfl_xor_sync(0xffffffffu, s, o);
    float lse = m + logf(s);
    out[(size_t)warp * T_TAGS + lane] = a - lse;
    out[(size_t)warp * T_TAGS + lane + 32] = b - lse;
}

/* ------------------- launcher --------------------------------------------- */
extern "C" void kernel_launch(void* const* d_in, const int* in_sizes, int n_in,
                              void* d_out, int out_size) {
    const int*   sentence  = (const int*)d_in[0];
    const int*   charsets  = (const int*)d_in[1];
    const int*   lengths   = (const int*)d_in[2];
    const float* word_emb  = (const float*)d_in[3];
    const float* char_emb  = (const float*)d_in[4];
    const float* cWih      = (const float*)d_in[5];
    const float* cWhh      = (const float*)d_in[6];
    const float* cb        = (const float*)d_in[7];
    const float* fWih      = (const float*)d_in[8];
    const float* fWhh      = (const float*)d_in[9];
    const float* fb        = (const float*)d_in[10];
    const float* bWih      = (const float*)d_in[11];
    const float* bWhh      = (const float*)d_in[12];
    const float* bb        = (const float*)d_in[13];
    const float* outW      = (const float*)d_in[14];
    const float* outb      = (const float*)d_in[15];
    float* out = (float*)d_out;

    void *pXc, *pIdx, *pGates, *pHc, *pEmb, *pGf, *pGb, *pLout, *pLog;
    cudaGetSymbolAddress(&pXc, g_Xc);
    cudaGetSymbolAddress(&pIdx, g_charidx);
    cudaGetSymbolAddress(&pGates, g_gates);
    cudaGetSymbolAddress(&pHc, g_Hc);
    cudaGetSymbolAddress(&pEmb, g_embeds);
    cudaGetSymbolAddress(&pGf, g_Gf);
    cudaGetSymbolAddress(&pGb, g_Gb);
    cudaGetSymbolAddress(&pLout, g_lstm_out);
    cudaGetSymbolAddress(&pLog, g_logits);

    /* reset per-launch state (graph-replay determinism) */
    init_state<<<2048, 256>>>();

    /* char LSTM input projection for all (t,w): gather + GEMM */
    build_charidx<<<(LCC * S_LEN + 255) / 256, 256>>>(charsets);
    gemm_tn<<<dim3(4 * HC / 64, LCC * S_LEN / 64), 256>>>(
        char_emb, DC, cWih, cb, (float*)pXc,
        LCC * S_LEN, 4 * HC, DC, (const int*)pIdx, 0);

    /* char LSTM: 16 time steps, batched over S */
    for (int t = 0; t < LCC; t++) {
        gemm_tn<<<dim3(4 * HC / 64, S_LEN / 64), 256>>>(
            (const float*)pHc, HC, cWhh, nullptr, (float*)pGates,
            S_LEN, 4 * HC, HC, nullptr, 0);
        char_update<<<S_LEN * HC / 256, 256>>>(lengths, t);
    }

    /* embeds + main input projections */
    build_embeds<<<S_LEN * KIN / 256, 256>>>(sentence, word_emb);
    gemm_tn<<<dim3(4 * H2 / 64, S_LEN / 64), 256>>>(
        (const float*)pEmb, KIN, fWih, fb, (float*)pGf,
        S_LEN, 4 * H2, KIN, nullptr, 0);
    gemm_tn<<<dim3(4 * H2 / 64, S_LEN / 64), 256>>>(
        (const float*)pEmb, KIN, bWih, bb, (float*)pGb,
        S_LEN, 4 * H2, KIN, nullptr, 1);

    /* sequential bidirectional recurrence: 2 clusters of 8 CTAs */
    recurrent_cluster<<<2 * NBC, RT2>>>(fWhh, bWhh);

    /* output projection + log_softmax */
    gemm_tn<<<dim3(T_TAGS / 64, S_LEN / 64), 256>>>(
        (const float*)pLout, HH, outW, outb, (float*)pLog,
        S_LEN, T_TAGS, HH, nullptr, 0);
    logsoftmax_kernel<<<(S_LEN * 32 + 255) / 256, 256>>>(out);
}

// round 10
// speedup vs baseline: 1.9795x; 1.9795x over previous
#include <cuda_runtime.h>
#include <math.h>
#include <stdint.h>

#define S_LEN 8192
#define LCC   16
#define DW    256
#define DC    64
#define HC    128
#define HH    512
#define T_TAGS 64
#define H2    256
#define KIN   384      /* HC + DW */
#define NBC   8        /* CTAs per direction (one portable cluster) */
#define RT2   256      /* 8 warps per CTA; each warp owns 4 h-units */

/* ------------------- scratch (device globals; no allocation) ------------- */
__device__ float g_Xc[(size_t)LCC * S_LEN * 4 * HC];
__device__ int   g_charidx[LCC * S_LEN];
__device__ float g_gates[S_LEN * 4 * HC];
__device__ float g_Hc[S_LEN * HC];
__device__ float g_Cc[S_LEN * HC];
__device__ float g_charfeat[S_LEN * HC];
__device__ float g_embeds[S_LEN * KIN];
__device__ float g_Gf[(size_t)S_LEN * 4 * H2];
__device__ float g_Gb[(size_t)S_LEN * 4 * H2];
__device__ float g_lstm_out[S_LEN * HH];
__device__ float g_logits[S_LEN * T_TAGS];

__device__ __forceinline__ float sigf(float x) { return 1.0f / (1.0f + expf(-x)); }

/* fast gates: hardware MUFU tanh (sm_75+); sigmoid via tanh identity */
__device__ __forceinline__ float tanh_fast(float x) {
    float y;
    asm("tanh.approx.f32 %0, %1;" : "=f"(y) : "f"(x));
    return y;
}
__device__ __forceinline__ float sig_fast(float x) {
    return fmaf(tanh_fast(0.5f * x), 0.5f, 0.5f);
}

/* ---- PTX helpers ---- */
__device__ __forceinline__ uint32_t smem_u32(const void* p) {
    uint32_t a;
    asm("{ .reg .u64 t; cvta.to.shared.u64 t, %1; cvt.u32.u64 %0, t; }" : "=r"(a) : "l"(p));
    return a;
}
__device__ __forceinline__ uint32_t mapa_rank(uint32_t addr, uint32_t rank) {
    uint32_t r;
    asm("mapa.shared::cluster.u32 %0, %1, %2;" : "=r"(r) : "r"(addr), "r"(rank));
    return r;
}
__device__ __forceinline__ void mbar_wait_acq(uint32_t mbar, uint32_t parity) {
    uint32_t done;
    asm volatile(
        "{\n\t.reg .pred p;\n\t"
        "mbarrier.try_wait.parity.acquire.cluster.shared::cta.b64 p, [%1], %2;\n\t"
        "selp.b32 %0, 1, 0, p;\n\t}"
        : "=r"(done) : "r"(mbar), "r"(parity) : "memory");
    while (!done) {
        asm volatile(
            "{\n\t.reg .pred p;\n\t"
            "mbarrier.try_wait.parity.acquire.cluster.shared::cta.b64 p, [%1], %2, 0x989680;\n\t"
            "selp.b32 %0, 1, 0, p;\n\t}"
            : "=r"(done) : "r"(mbar), "r"(parity) : "memory");
    }
}
__device__ __forceinline__ void mbar_arm(uint32_t mbar, uint32_t tx) {
    asm volatile("mbarrier.arrive.expect_tx.shared::cta.b64 _, [%0], %1;"
                 :: "r"(mbar), "r"(tx) : "memory");
}
__device__ __forceinline__ void st_async_v2b64(uint32_t raddr, unsigned long long v0,
                                               unsigned long long v1, uint32_t rmbar) {
    asm volatile(
        "st.async.shared::cluster.mbarrier::complete_tx::bytes.v2.b64 [%0], {%1, %2}, [%3];"
        :: "r"(raddr), "l"(v0), "l"(v1), "r"(rmbar) : "memory");
}
#define FMA2(acc, a, b) asm("fma.rn.f32x2 %0, %1, %2, %0;" : "+l"(acc) : "l"(a), "l"(b))
#define UNPACK2(lo, hi, v) asm("mov.b64 {%0,%1}, %2;" : "=f"(lo), "=f"(hi) : "l"(v))

/* ------------------- init: must run every launch (graph determinism) ----- */
__global__ void init_state() {
    int idx = blockIdx.x * blockDim.x + threadIdx.x;
    int stride = gridDim.x * blockDim.x;
    for (int i = idx; i < S_LEN * HC; i += stride) {
        g_Hc[i] = 0.0f;
        g_Cc[i] = 0.0f;
    }
}

__global__ void build_charidx(const int* __restrict__ charsets) {
    int idx = blockIdx.x * blockDim.x + threadIdx.x;
    if (idx >= LCC * S_LEN) return;
    int t = idx / S_LEN;
    int w = idx - t * S_LEN;
    g_charidx[idx] = charsets[w * LCC + t];
}

/* ------------------- generic fp32 GEMM ------------------------------------ */
__global__ void __launch_bounds__(256) gemm_tn(
    const float* __restrict__ A, int lda,
    const float* __restrict__ B,
    const float* __restrict__ bias,
    float* __restrict__ C, int M, int N, int K,
    const int* __restrict__ gidx, int rev)
{
    __shared__ float4 As4[16 * 16];
    __shared__ float4 Bs4[16 * 16];
    float* As = (float*)As4;
    float* Bs = (float*)Bs4;

    int tid = threadIdx.x;
    int m0 = blockIdx.y * 64, n0 = blockIdx.x * 64;
    int lm = tid >> 2;
    int kq = tid & 3;

    int mg = m0 + lm;
    int arow = gidx ? gidx[mg] : (rev ? (M - 1 - mg) : mg);
    const float* Ap = A + (size_t)arow * lda;
    const float* Bp = B + (size_t)(n0 + lm) * K;

    int ty = tid >> 4, tx = tid & 15;
    float acc[4][4];
#pragma unroll
    for (int i = 0; i < 4; i++)
#pragma unroll
        for (int j = 0; j < 4; j++) acc[i][j] = 0.0f;

    for (int k0 = 0; k0 < K; k0 += 16) {
        float4 a = *(const float4*)(Ap + k0 + kq * 4);
        float4 b = *(const float4*)(Bp + k0 + kq * 4);
        __syncthreads();
        As[(kq * 4 + 0) * 64 + lm] = a.x;
        As[(kq * 4 + 1) * 64 + lm] = a.y;
        As[(kq * 4 + 2) * 64 + lm] = a.z;
        As[(kq * 4 + 3) * 64 + lm] = a.w;
        Bs[(kq * 4 + 0) * 64 + lm] = b.x;
        Bs[(kq * 4 + 1) * 64 + lm] = b.y;
        Bs[(kq * 4 + 2) * 64 + lm] = b.z;
        Bs[(kq * 4 + 3) * 64 + lm] = b.w;
        __syncthreads();
#pragma unroll
        for (int kk = 0; kk < 16; kk++) {
            float4 av = As4[kk * 16 + ty];
            float4 bv = Bs4[kk * 16 + tx];
            acc[0][0] += av.x * bv.x; acc[0][1] += av.x * bv.y;
            acc[0][2] += av.x * bv.z; acc[0][3] += av.x * bv.w;
            acc[1][0] += av.y * bv.x; acc[1][1] += av.y * bv.y;
            acc[1][2] += av.y * bv.z; acc[1][3] += av.y * bv.w;
            acc[2][0] += av.z * bv.x; acc[2][1] += av.z * bv.y;
            acc[2][2] += av.z * bv.z; acc[2][3] += av.z * bv.w;
            acc[3][0] += av.w * bv.x; acc[3][1] += av.w * bv.y;
            acc[3][2] += av.w * bv.z; acc[3][3] += av.w * bv.w;
        }
    }
#pragma unroll
    for (int i = 0; i < 4; i++) {
        int m = m0 + ty * 4 + i;
        int n = n0 + tx * 4;
        float4 o;
        o.x = acc[i][0]; o.y = acc[i][1]; o.z = acc[i][2]; o.w = acc[i][3];
        if (bias) {
            o.x += bias[n + 0]; o.y += bias[n + 1];
            o.z += bias[n + 2]; o.w += bias[n + 3];
        }
        *(float4*)(C + (size_t)m * N + n) = o;
    }
}

/* ------------------- char LSTM pointwise update (accurate math) ----------- */
__global__ void char_update(const int* __restrict__ lengths, int t) {
    int idx = blockIdx.x * blockDim.x + threadIdx.x;
    if (idx >= S_LEN * HC) return;
    int w = idx / HC, u = idx - w * HC;
    const float* xrow = g_Xc + ((size_t)t * S_LEN + w) * (4 * HC);
    const float* grow = g_gates + (size_t)w * (4 * HC);
    float gi = grow[0 * HC + u] + xrow[0 * HC + u];
    float gf = grow[1 * HC + u] + xrow[1 * HC + u];
    float gg = grow[2 * HC + u] + xrow[2 * HC + u];
    float go = grow[3 * HC + u] + xrow[3 * HC + u];
    float c = g_Cc[idx];
    c = sigf(gf) * c + sigf(gi) * tanhf(gg);
    float h = sigf(go) * tanhf(c);
    g_Cc[idx] = c;
    g_Hc[idx] = h;
    if (t == lengths[w] - 1) g_charfeat[idx] = h;
}

/* ------------------- embeds = [charfeat | word_emb[sentence]] ------------- */
__global__ void build_embeds(const int* __restrict__ sentence,
                             const float* __restrict__ word_emb) {
    int idx = blockIdx.x * blockDim.x + threadIdx.x;
    if (idx >= S_LEN * KIN) return;
    int w = idx / KIN, j = idx - w * KIN;
    float v;
    if (j < HC) v = g_charfeat[w * HC + j];
    else        v = word_emb[(size_t)sentence[w] * DW + (j - HC)];
    g_embeds[idx] = v;
}

/* ------------------- barrier-free cluster recurrence (R4 skeleton) --------
 * 2 clusters of 8 CTAs (one per direction), 256 threads = 8 warps/CTA.
 * Each WARP owns 4 h-units end-to-end:
 *   lane = r_l*2 + seg; r_l in [0,16) = 4 units x 4 gates; seg = k half.
 *   dot: 64 FMA2/lane over 128 k-values; 1 xor-shfl (seg) reduce;
 *   4 idx-shfls gather this lane's unit gates; fast MUFU tanh gate math
 *   (redundant in-lane); 3 shfls gather the warp's 4 h values; lane 0
 *   pushes ONE 16-B st.async.v2.b64 to each of 8 peer CTAs.
 * Receiver: 64 tx events x 16 B per step (vs 128 x 8 B before), two
 * alternating expect_tx(1024) mbarriers, re-armed by tid0 after wait.
 * No __syncthreads / cluster barrier / L1 flush in the step loop.        */
__global__ void __launch_bounds__(RT2, 1) __cluster_dims__(NBC, 1, 1)
recurrent_cluster(const float* __restrict__ WhhF, const float* __restrict__ WhhB)
{
    __shared__ __align__(16) float s_h[2][H2];
    __shared__ __align__(8) unsigned long long s_mbar[2];

    int tid = threadIdx.x;
    int wid = tid >> 5;
    int lane = tid & 31;
    int d = blockIdx.x >> 3;
    int b = blockIdx.x & 7;
    const float* Whh = d ? WhhB : WhhF;
    const float* G = d ? g_Gb : g_Gf;

    int seg = lane & 1;            /* k half 0..1                    */
    int r_l = lane >> 1;           /* 0..15: ul = r_l>>2, gk = r_l&3 */
    int ul = r_l >> 2;
    int gk = r_l & 3;
    int u = b * 32 + wid * 4 + ul; /* global h-unit of this lane     */
    int row = gk * H2 + u;         /* gate row                       */

    /* 128 weights per lane, packed f32x2; k interleaved by float4(seg) */
    ulonglong2 w[32];
    const float* wrow = Whh + (size_t)row * H2;
#pragma unroll
    for (int jj = 0; jj < 32; jj++)
        w[jj] = *reinterpret_cast<const ulonglong2*>(wrow + (jj * 2 + seg) * 4);

    if (tid < H2) { s_h[0][tid] = 0.0f; s_h[1][tid] = 0.0f; }

    uint32_t mb0 = smem_u32(&s_mbar[0]);
    uint32_t mb1 = smem_u32(&s_mbar[1]);
    if (tid == 0) {
        asm volatile("mbarrier.init.shared.b64 [%0], %1;" :: "r"(mb0), "r"(1) : "memory");
        asm volatile("mbarrier.init.shared.b64 [%0], %1;" :: "r"(mb1), "r"(1) : "memory");
        mbar_arm(mb0, 1024);   /* receives wave 1 */
        mbar_arm(mb1, 1024);   /* receives wave 0 */
        asm volatile("fence.mbarrier_init.release.cluster;" ::: "memory");
    }

    /* lane-0 pushers: remote h-buffer slots + remote mbarriers, all 8 peers */
    uint32_t rh0[NBC], rh1[NBC], rm0[NBC], rm1[NBC];
    if (lane == 0) {
        uint32_t off = (uint32_t)(b * 32 + wid * 4) * 4u;
        uint32_t h0 = smem_u32(&s_h[0][0]) + off;
        uint32_t h1 = smem_u32(&s_h[1][0]) + off;
#pragma unroll
        for (int p = 0; p < NBC; p++) {
            rh0[p] = mapa_rank(h0, (uint32_t)p);
            rh1[p] = mapa_rank(h1, (uint32_t)p);
            rm0[p] = mapa_rank(mb0, (uint32_t)p);
            rm1[p] = mapa_rank(mb1, (uint32_t)p);
        }
    }

    __syncthreads();
    asm volatile("barrier.cluster.arrive.aligned;" ::: "memory");
    asm volatile("barrier.cluster.wait.aligned;" ::: "memory");

    uint32_t ph0 = 0, ph1 = 0;
    float c = 0.0f;
    float gin = 0.0f;
    if (seg == 0) gin = G[row];    /* prefetch t=0 */

    for (int t = 0; t < S_LEN; t++) {
        int idx = t & 1;
        if (t > 0) {
            uint32_t mb = idx ? mb1 : mb0;
            uint32_t ph = idx ? ph1 : ph0;
            mbar_wait_acq(mb, ph);
            if (idx) ph1 ^= 1; else ph0 ^= 1;
            if (tid == 0) mbar_arm(mb, 1024);   /* re-arm for wave t+2 */
        }

        const float* hb = s_h[idx];
        unsigned long long acc0 = 0ull, acc1 = 0ull;
#pragma unroll
        for (int jj = 0; jj < 32; jj++) {
            ulonglong2 hv = *reinterpret_cast<const ulonglong2*>(hb + (jj * 2 + seg) * 4);
            FMA2(acc0, w[jj].x, hv.x);
            FMA2(acc1, w[jj].y, hv.y);
        }
        float a0, a1, a2, a3;
        UNPACK2(a0, a1, acc0);
        UNPACK2(a2, a3, acc1);
        float acc = (a0 + a1) + (a2 + a3);
        acc += __shfl_xor_sync(0xffffffffu, acc, 1);   /* reduce k halves */
        if (seg == 0) acc += gin;                      /* +input proj     */

        /* gather this lane's unit gates (sources: even lanes) */
        int base = lane & 24;                          /* (lane>>3)*8     */
        float gi = __shfl_sync(0xffffffffu, acc, base + 0);
        float gf = __shfl_sync(0xffffffffu, acc, base + 2);
        float gg = __shfl_sync(0xffffffffu, acc, base + 4);
        float go = __shfl_sync(0xffffffffu, acc, base + 6);

        c = sig_fast(gf) * c + sig_fast(gi) * tanh_fast(gg);
        float h = sig_fast(go) * tanh_fast(c);

        if (seg == 0 && t + 1 < S_LEN)
            gin = G[(size_t)(t + 1) * (4 * H2) + row]; /* prefetch next   */

        if ((lane & 7) == 0) {                 /* lanes 0,8,16,24: 4 units */
            int outrow = d ? (S_LEN - 1 - t) : t;
            g_lstm_out[(size_t)outrow * HH + d * H2 + u] = h;
        }
        /* gather warp's 4 h values into lane 0 and push 16 B to each peer */
        float hB = __shfl_sync(0xffffffffu, h, 8);
        float hC = __shfl_sync(0xffffffffu, h, 16);
        float hD = __shfl_sync(0xffffffffu, h, 24);

        if (lane == 0 && t + 1 < S_LEN) {
            unsigned long long p0, p1;
            asm("mov.b64 %0, {%1,%2};" : "=l"(p0) : "f"(h), "f"(hB));
            asm("mov.b64 %0, {%1,%2};" : "=l"(p1) : "f"(hC), "f"(hD));
            if (idx) {          /* dst buffer 0, mbar 0 */
#pragma unroll
                for (int p = 0; p < NBC; p++) st_async_v2b64(rh0[p], p0, p1, rm0[p]);
            } else {            /* dst buffer 1, mbar 1 */
#pragma unroll
                for (int p = 0; p < NBC; p++) st_async_v2b64(rh1[p], p0, p1, rm1[p]);
            }
        }
    }

    asm volatile("barrier.cluster.arrive.aligned;" ::: "memory");
    asm volatile("barrier.cluster.wait.aligned;" ::: "memory");
}

/* ------------------- log_softmax over 64 tags (one warp per word) --------- */
__global__ void logsoftmax_kernel(float* __restrict__ out) {
    int gt = blockIdx.x * blockDim.x + threadIdx.x;
    int warp = gt >> 5;
    int lane = gt & 31;
    if (warp >= S_LEN) return;
    const float* l = g_logits + (size_t)warp * T_TAGS;
    float a = l[lane], b = l[lane + 32];
    float m = fmaxf(a, b);
#pragma unroll
    for (int o = 16; o > 0; o >>= 1) m = fmaxf(m, __shfl_xor_sync(0xffffffffu, m, o));
    float s = expf(a - m) + expf(b - m);
#pragma unroll
    for (int o = 16; o > 0; o >>= 1) s += __shfl_xor_sync(0xffffffffu, s, o);
    float lse = m + logf(s);
    out[(size_t)warp * T_TAGS + lane] = a - lse;
    out[(size_t)warp * T_TAGS + lane + 32] = b - lse;
}

/* ------------------- launcher --------------------------------------------- */
extern "C" void kernel_launch(void* const* d_in, const int* in_sizes, int n_in,
                              void* d_out, int out_size) {
    const int*   sentence  = (const int*)d_in[0];
    const int*   charsets  = (const int*)d_in[1];
    const int*   lengths   = (const int*)d_in[2];
    const float* word_emb  = (const float*)d_in[3];
    const float* char_emb  = (const float*)d_in[4];
    const float* cWih      = (const float*)d_in[5];
    const float* cWhh      = (const float*)d_in[6];
    const float* cb        = (const float*)d_in[7];
    const float* fWih      = (const float*)d_in[8];
    const float* fWhh      = (const float*)d_in[9];
    const float* fb        = (const float*)d_in[10];
    const float* bWih      = (const float*)d_in[11];
    const float* bWhh      = (const float*)d_in[12];
    const float* bb        = (const float*)d_in[13];
    const float* outW      = (const float*)d_in[14];
    const float* outb      = (const float*)d_in[15];
    float* out = (float*)d_out;

    void *pXc, *pIdx, *pGates, *pHc, *pEmb, *pGf, *pGb, *pLout, *pLog;
    cudaGetSymbolAddress(&pXc, g_Xc);
    cudaGetSymbolAddress(&pIdx, g_charidx);
    cudaGetSymbolAddress(&pGates, g_gates);
    cudaGetSymbolAddress(&pHc, g_Hc);
    cudaGetSymbolAddress(&pEmb, g_embeds);
    cudaGetSymbolAddress(&pGf, g_Gf);
    cudaGetSymbolAddress(&pGb, g_Gb);
    cudaGetSymbolAddress(&pLout, g_lstm_out);
    cudaGetSymbolAddress(&pLog, g_logits);

    /* reset per-launch state (graph-replay determinism) */
    init_state<<<2048, 256>>>();

    /* char LSTM input projection for all (t,w): gather + GEMM */
    build_charidx<<<(LCC * S_LEN + 255) / 256, 256>>>(charsets);
    gemm_tn<<<dim3(4 * HC / 64, LCC * S_LEN / 64), 256>>>(
        char_emb, DC, cWih, cb, (float*)pXc,
        LCC * S_LEN, 4 * HC, DC, (const int*)pIdx, 0);

    /* char LSTM: 16 time steps, batched over S */
    for (int t = 0; t < LCC; t++) {
        gemm_tn<<<dim3(4 * HC / 64, S_LEN / 64), 256>>>(
            (const float*)pHc, HC, cWhh, nullptr, (float*)pGates,
            S_LEN, 4 * HC, HC, nullptr, 0);
        char_update<<<S_LEN * HC / 256, 256>>>(lengths, t);
    }

    /* embeds + main input projections */
    build_embeds<<<S_LEN * KIN / 256, 256>>>(sentence, word_emb);
    gemm_tn<<<dim3(4 * H2 / 64, S_LEN / 64), 256>>>(
        (const float*)pEmb, KIN, fWih, fb, (float*)pGf,
        S_LEN, 4 * H2, KIN, nullptr, 0);
    gemm_tn<<<dim3(4 * H2 / 64, S_LEN / 64), 256>>>(
        (const float*)pEmb, KIN, bWih, bb, (float*)pGb,
        S_LEN, 4 * H2, KIN, nullptr, 1);

    /* sequential bidirectional recurrence: 2 clusters of 8 CTAs */
    recurrent_cluster<<<2 * NBC, RT2>>>(fWhh, bWhh);

    /* output projection + log_softmax */
    gemm_tn<<<dim3(T_TAGS / 64, S_LEN / 64), 256>>>(
        (const float*)pLout, HH, outW, outb, (float*)pLog,
        S_LEN, T_TAGS, HH, nullptr, 0);
    logsoftmax_kernel<<<(S_LEN * 32 + 255) / 256, 256>>>(out);
}

// round 11
// speedup vs baseline: 2.2644x; 1.1439x over previous
#include <cuda_runtime.h>
#include <math.h>
#include <stdint.h>

#define S_LEN 8192
#define LCC   16
#define DW    256
#define DC    64
#define HC    128
#define HH    512
#define T_TAGS 64
#define H2    256
#define KIN   384      /* HC + DW */
#define NBC   16       /* CTAs per direction (nonportable cluster of 16) */
#define RT2   128      /* 4 warps per CTA; each warp owns 4 h-units */

/* ------------------- scratch (device globals; no allocation) ------------- */
__device__ float g_Xc[(size_t)LCC * S_LEN * 4 * HC];
__device__ int   g_charidx[LCC * S_LEN];
__device__ float g_gates[S_LEN * 4 * HC];
__device__ float g_Hc[S_LEN * HC];
__device__ float g_Cc[S_LEN * HC];
__device__ float g_charfeat[S_LEN * HC];
__device__ float g_embeds[S_LEN * KIN];
__device__ float g_Gf[(size_t)S_LEN * 4 * H2];
__device__ float g_Gb[(size_t)S_LEN * 4 * H2];
__device__ float g_lstm_out[S_LEN * HH];
__device__ float g_logits[S_LEN * T_TAGS];

__device__ __forceinline__ float sigf(float x) { return 1.0f / (1.0f + expf(-x)); }

/* fast gates: hardware MUFU tanh (sm_75+); sigmoid via tanh identity */
__device__ __forceinline__ float tanh_fast(float x) {
    float y;
    asm("tanh.approx.f32 %0, %1;" : "=f"(y) : "f"(x));
    return y;
}
__device__ __forceinline__ float sig_fast(float x) {
    return fmaf(tanh_fast(0.5f * x), 0.5f, 0.5f);
}

/* ---- PTX helpers ---- */
__device__ __forceinline__ uint32_t smem_u32(const void* p) {
    uint32_t a;
    asm("{ .reg .u64 t; cvta.to.shared.u64 t, %1; cvt.u32.u64 %0, t; }" : "=r"(a) : "l"(p));
    return a;
}
__device__ __forceinline__ uint32_t mapa_rank(uint32_t addr, uint32_t rank) {
    uint32_t r;
    asm("mapa.shared::cluster.u32 %0, %1, %2;" : "=r"(r) : "r"(addr), "r"(rank));
    return r;
}
__device__ __forceinline__ void mbar_wait_acq(uint32_t mbar, uint32_t parity) {
    uint32_t done;
    asm volatile(
        "{\n\t.reg .pred p;\n\t"
        "mbarrier.try_wait.parity.acquire.cluster.shared::cta.b64 p, [%1], %2;\n\t"
        "selp.b32 %0, 1, 0, p;\n\t}"
        : "=r"(done) : "r"(mbar), "r"(parity) : "memory");
    while (!done) {
        asm volatile(
            "{\n\t.reg .pred p;\n\t"
            "mbarrier.try_wait.parity.acquire.cluster.shared::cta.b64 p, [%1], %2, 0x989680;\n\t"
            "selp.b32 %0, 1, 0, p;\n\t}"
            : "=r"(done) : "r"(mbar), "r"(parity) : "memory");
    }
}
__device__ __forceinline__ void mbar_arm(uint32_t mbar, uint32_t tx) {
    asm volatile("mbarrier.arrive.expect_tx.shared::cta.b64 _, [%0], %1;"
                 :: "r"(mbar), "r"(tx) : "memory");
}
__device__ __forceinline__ void st_async_v2b64(uint32_t raddr, unsigned long long v0,
                                               unsigned long long v1, uint32_t rmbar) {
    asm volatile(
        "st.async.shared::cluster.mbarrier::complete_tx::bytes.v2.b64 [%0], {%1, %2}, [%3];"
        :: "r"(raddr), "l"(v0), "l"(v1), "r"(rmbar) : "memory");
}
#define FMA2(acc, a, b) asm("fma.rn.f32x2 %0, %1, %2, %0;" : "+l"(acc) : "l"(a), "l"(b))
#define UNPACK2(lo, hi, v) asm("mov.b64 {%0,%1}, %2;" : "=f"(lo), "=f"(hi) : "l"(v))

/* ------------------- init: must run every launch (graph determinism) ----- */
__global__ void init_state() {
    int idx = blockIdx.x * blockDim.x + threadIdx.x;
    int stride = gridDim.x * blockDim.x;
    for (int i = idx; i < S_LEN * HC; i += stride) {
        g_Hc[i] = 0.0f;
        g_Cc[i] = 0.0f;
    }
}

__global__ void build_charidx(const int* __restrict__ charsets) {
    int idx = blockIdx.x * blockDim.x + threadIdx.x;
    if (idx >= LCC * S_LEN) return;
    int t = idx / S_LEN;
    int w = idx - t * S_LEN;
    g_charidx[idx] = charsets[w * LCC + t];
}

/* ------------------- generic fp32 GEMM ------------------------------------ */
__global__ void __launch_bounds__(256) gemm_tn(
    const float* __restrict__ A, int lda,
    const float* __restrict__ B,
    const float* __restrict__ bias,
    float* __restrict__ C, int M, int N, int K,
    const int* __restrict__ gidx, int rev)
{
    __shared__ float4 As4[16 * 16];
    __shared__ float4 Bs4[16 * 16];
    float* As = (float*)As4;
    float* Bs = (float*)Bs4;

    int tid = threadIdx.x;
    int m0 = blockIdx.y * 64, n0 = blockIdx.x * 64;
    int lm = tid >> 2;
    int kq = tid & 3;

    int mg = m0 + lm;
    int arow = gidx ? gidx[mg] : (rev ? (M - 1 - mg) : mg);
    const float* Ap = A + (size_t)arow * lda;
    const float* Bp = B + (size_t)(n0 + lm) * K;

    int ty = tid >> 4, tx = tid & 15;
    float acc[4][4];
#pragma unroll
    for (int i = 0; i < 4; i++)
#pragma unroll
        for (int j = 0; j < 4; j++) acc[i][j] = 0.0f;

    for (int k0 = 0; k0 < K; k0 += 16) {
        float4 a = *(const float4*)(Ap + k0 + kq * 4);
        float4 b = *(const float4*)(Bp + k0 + kq * 4);
        __syncthreads();
        As[(kq * 4 + 0) * 64 + lm] = a.x;
        As[(kq * 4 + 1) * 64 + lm] = a.y;
        As[(kq * 4 + 2) * 64 + lm] = a.z;
        As[(kq * 4 + 3) * 64 + lm] = a.w;
        Bs[(kq * 4 + 0) * 64 + lm] = b.x;
        Bs[(kq * 4 + 1) * 64 + lm] = b.y;
        Bs[(kq * 4 + 2) * 64 + lm] = b.z;
        Bs[(kq * 4 + 3) * 64 + lm] = b.w;
        __syncthreads();
#pragma unroll
        for (int kk = 0; kk < 16; kk++) {
            float4 av = As4[kk * 16 + ty];
            float4 bv = Bs4[kk * 16 + tx];
            acc[0][0] += av.x * bv.x; acc[0][1] += av.x * bv.y;
            acc[0][2] += av.x * bv.z; acc[0][3] += av.x * bv.w;
            acc[1][0] += av.y * bv.x; acc[1][1] += av.y * bv.y;
            acc[1][2] += av.y * bv.z; acc[1][3] += av.y * bv.w;
            acc[2][0] += av.z * bv.x; acc[2][1] += av.z * bv.y;
            acc[2][2] += av.z * bv.z; acc[2][3] += av.z * bv.w;
            acc[3][0] += av.w * bv.x; acc[3][1] += av.w * bv.y;
            acc[3][2] += av.w * bv.z; acc[3][3] += av.w * bv.w;
        }
    }
#pragma unroll
    for (int i = 0; i < 4; i++) {
        int m = m0 + ty * 4 + i;
        int n = n0 + tx * 4;
        float4 o;
        o.x = acc[i][0]; o.y = acc[i][1]; o.z = acc[i][2]; o.w = acc[i][3];
        if (bias) {
            o.x += bias[n + 0]; o.y += bias[n + 1];
            o.z += bias[n + 2]; o.w += bias[n + 3];
        }
        *(float4*)(C + (size_t)m * N + n) = o;
    }
}

/* ------------------- char LSTM pointwise update (accurate math) ----------- */
__global__ void char_update(const int* __restrict__ lengths, int t) {
    int idx = blockIdx.x * blockDim.x + threadIdx.x;
    if (idx >= S_LEN * HC) return;
    int w = idx / HC, u = idx - w * HC;
    const float* xrow = g_Xc + ((size_t)t * S_LEN + w) * (4 * HC);
    const float* grow = g_gates + (size_t)w * (4 * HC);
    float gi = grow[0 * HC + u] + xrow[0 * HC + u];
    float gf = grow[1 * HC + u] + xrow[1 * HC + u];
    float gg = grow[2 * HC + u] + xrow[2 * HC + u];
    float go = grow[3 * HC + u] + xrow[3 * HC + u];
    float c = g_Cc[idx];
    c = sigf(gf) * c + sigf(gi) * tanhf(gg);
    float h = sigf(go) * tanhf(c);
    g_Cc[idx] = c;
    g_Hc[idx] = h;
    if (t == lengths[w] - 1) g_charfeat[idx] = h;
}

/* ------------------- embeds = [charfeat | word_emb[sentence]] ------------- */
__global__ void build_embeds(const int* __restrict__ sentence,
                             const float* __restrict__ word_emb) {
    int idx = blockIdx.x * blockDim.x + threadIdx.x;
    if (idx >= S_LEN * KIN) return;
    int w = idx / KIN, j = idx - w * KIN;
    float v;
    if (j < HC) v = g_charfeat[w * HC + j];
    else        v = word_emb[(size_t)sentence[w] * DW + (j - HC)];
    g_embeds[idx] = v;
}

/* ------------------- barrier-free cluster recurrence ----------------------
 * 2 nonportable clusters of 16 CTAs (one per direction), 128 threads =
 * 4 warps/CTA (1 warp per SMSP -> dot issue pressure halved vs 8x256).
 * Each WARP owns 4 h-units end-to-end (same layout as before):
 *   lane = r_l*2 + seg; r_l in [0,16) = 4 units x 4 gates; seg = k half.
 *   dot: 64 FMA2/lane; 1 xor-shfl reduce; 4 idx-shfls gate gather;
 *   fast MUFU tanh gate math; 3 shfls h gather; lane 0 pushes ONE 16-B
 *   st.async.v2.b64 to each of 16 peer CTAs.
 * Receiver: 64 tx events x 16 B per step, two alternating expect_tx(1024)
 * mbarriers re-armed by tid0 after wait. No syncthreads in the loop.      */
__global__ void __launch_bounds__(RT2, 1) __cluster_dims__(NBC, 1, 1)
recurrent_cluster(const float* __restrict__ WhhF, const float* __restrict__ WhhB)
{
    __shared__ __align__(16) float s_h[2][H2];
    __shared__ __align__(8) unsigned long long s_mbar[2];

    int tid = threadIdx.x;
    int wid = tid >> 5;
    int lane = tid & 31;
    int d = blockIdx.x >> 4;       /* cluster id = direction        */
    int b = blockIdx.x & 15;       /* rank within cluster           */
    const float* Whh = d ? WhhB : WhhF;
    const float* G = d ? g_Gb : g_Gf;

    int seg = lane & 1;            /* k half 0..1                    */
    int r_l = lane >> 1;           /* 0..15: ul = r_l>>2, gk = r_l&3 */
    int ul = r_l >> 2;
    int gk = r_l & 3;
    int u = b * 16 + wid * 4 + ul; /* global h-unit of this lane     */
    int row = gk * H2 + u;         /* gate row                       */

    /* 128 weights per lane, packed f32x2; k interleaved by float4(seg) */
    ulonglong2 w[32];
    const float* wrow = Whh + (size_t)row * H2;
#pragma unroll
    for (int jj = 0; jj < 32; jj++)
        w[jj] = *reinterpret_cast<const ulonglong2*>(wrow + (jj * 2 + seg) * 4);

    for (int i = tid; i < H2; i += RT2) { s_h[0][i] = 0.0f; s_h[1][i] = 0.0f; }

    uint32_t mb0 = smem_u32(&s_mbar[0]);
    uint32_t mb1 = smem_u32(&s_mbar[1]);
    if (tid == 0) {
        asm volatile("mbarrier.init.shared.b64 [%0], %1;" :: "r"(mb0), "r"(1) : "memory");
        asm volatile("mbarrier.init.shared.b64 [%0], %1;" :: "r"(mb1), "r"(1) : "memory");
        mbar_arm(mb0, 1024);   /* receives wave 1 */
        mbar_arm(mb1, 1024);   /* receives wave 0 */
        asm volatile("fence.mbarrier_init.release.cluster;" ::: "memory");
    }

    /* lane-0 pushers: remote h-buffer slots + remote mbarriers, 16 peers */
    uint32_t rh0[NBC], rh1[NBC], rm0[NBC], rm1[NBC];
    if (lane == 0) {
        uint32_t off = (uint32_t)(b * 16 + wid * 4) * 4u;
        uint32_t h0 = smem_u32(&s_h[0][0]) + off;
        uint32_t h1 = smem_u32(&s_h[1][0]) + off;
#pragma unroll
        for (int p = 0; p < NBC; p++) {
            rh0[p] = mapa_rank(h0, (uint32_t)p);
            rh1[p] = mapa_rank(h1, (uint32_t)p);
            rm0[p] = mapa_rank(mb0, (uint32_t)p);
            rm1[p] = mapa_rank(mb1, (uint32_t)p);
        }
    }

    __syncthreads();
    asm volatile("barrier.cluster.arrive.aligned;" ::: "memory");
    asm volatile("barrier.cluster.wait.aligned;" ::: "memory");

    uint32_t ph0 = 0, ph1 = 0;
    float c = 0.0f;
    float gin = 0.0f;
    if (seg == 0) gin = G[row];    /* prefetch t=0 */

    for (int t = 0; t < S_LEN; t++) {
        int idx = t & 1;
        if (t > 0) {
            uint32_t mb = idx ? mb1 : mb0;
            uint32_t ph = idx ? ph1 : ph0;
            mbar_wait_acq(mb, ph);
            if (idx) ph1 ^= 1; else ph0 ^= 1;
            if (tid == 0) mbar_arm(mb, 1024);   /* re-arm for wave t+2 */
        }

        const float* hb = s_h[idx];
        unsigned long long acc0 = 0ull, acc1 = 0ull;
#pragma unroll
        for (int jj = 0; jj < 32; jj++) {
            ulonglong2 hv = *reinterpret_cast<const ulonglong2*>(hb + (jj * 2 + seg) * 4);
            FMA2(acc0, w[jj].x, hv.x);
            FMA2(acc1, w[jj].y, hv.y);
        }
        float a0, a1, a2, a3;
        UNPACK2(a0, a1, acc0);
        UNPACK2(a2, a3, acc1);
        float acc = (a0 + a1) + (a2 + a3);
        acc += __shfl_xor_sync(0xffffffffu, acc, 1);   /* reduce k halves */
        if (seg == 0) acc += gin;                      /* +input proj     */

        /* gather this lane's unit gates (sources: even lanes) */
        int base = lane & 24;                          /* (lane>>3)*8     */
        float gi = __shfl_sync(0xffffffffu, acc, base + 0);
        float gf = __shfl_sync(0xffffffffu, acc, base + 2);
        float gg = __shfl_sync(0xffffffffu, acc, base + 4);
        float go = __shfl_sync(0xffffffffu, acc, base + 6);

        c = sig_fast(gf) * c + sig_fast(gi) * tanh_fast(gg);
        float h = sig_fast(go) * tanh_fast(c);

        if (seg == 0 && t + 1 < S_LEN)
            gin = G[(size_t)(t + 1) * (4 * H2) + row]; /* prefetch next   */

        if ((lane & 7) == 0) {                 /* lanes 0,8,16,24: 4 units */
            int outrow = d ? (S_LEN - 1 - t) : t;
            g_lstm_out[(size_t)outrow * HH + d * H2 + u] = h;
        }
        /* gather warp's 4 h values into lane 0 and push 16 B to each peer */
        float hB = __shfl_sync(0xffffffffu, h, 8);
        float hC = __shfl_sync(0xffffffffu, h, 16);
        float hD = __shfl_sync(0xffffffffu, h, 24);

        if (lane == 0 && t + 1 < S_LEN) {
            unsigned long long p0, p1;
            asm("mov.b64 %0, {%1,%2};" : "=l"(p0) : "f"(h), "f"(hB));
            asm("mov.b64 %0, {%1,%2};" : "=l"(p1) : "f"(hC), "f"(hD));
            if (idx) {          /* dst buffer 0, mbar 0 */
#pragma unroll
                for (int p = 0; p < NBC; p++) st_async_v2b64(rh0[p], p0, p1, rm0[p]);
            } else {            /* dst buffer 1, mbar 1 */
#pragma unroll
                for (int p = 0; p < NBC; p++) st_async_v2b64(rh1[p], p0, p1, rm1[p]);
            }
        }
    }

    asm volatile("barrier.cluster.arrive.aligned;" ::: "memory");
    asm volatile("barrier.cluster.wait.aligned;" ::: "memory");
}

/* ------------------- log_softmax over 64 tags (one warp per word) --------- */
__global__ void logsoftmax_kernel(float* __restrict__ out) {
    int gt = blockIdx.x * blockDim.x + threadIdx.x;
    int warp = gt >> 5;
    int lane = gt & 31;
    if (warp >= S_LEN) return;
    const float* l = g_logits + (size_t)warp * T_TAGS;
    float a = l[lane], b = l[lane + 32];
    float m = fmaxf(a, b);
#pragma unroll
    for (int o = 16; o > 0; o >>= 1) m = fmaxf(m, __shfl_xor_sync(0xffffffffu, m, o));
    float s = expf(a - m) + expf(b - m);
#pragma unroll
    for (int o = 16; o > 0; o >>= 1) s += __shfl_xor_sync(0xffffffffu, s, o);
    float lse = m + logf(s);
    out[(size_t)warp * T_TAGS + lane] = a - lse;
    out[(size_t)warp * T_TAGS + lane + 32] = b - lse;
}

/* ------------------- launcher --------------------------------------------- */
extern "C" void kernel_launch(void* const* d_in, const int* in_sizes, int n_in,
                              void* d_out, int out_size) {
    const int*   sentence  = (const int*)d_in[0];
    const int*   charsets  = (const int*)d_in[1];
    const int*   lengths   = (const int*)d_in[2];
    const float* word_emb  = (const float*)d_in[3];
    const float* char_emb  = (const float*)d_in[4];
    const float* cWih      = (const float*)d_in[5];
    const float* cWhh      = (const float*)d_in[6];
    const float* cb        = (const float*)d_in[7];
    const float* fWih      = (const float*)d_in[8];
    const float* fWhh      = (const float*)d_in[9];
    const float* fb        = (const float*)d_in[10];
    const float* bWih      = (const float*)d_in[11];
    const float* bWhh      = (const float*)d_in[12];
    const float* bb        = (const float*)d_in[13];
    const float* outW      = (const float*)d_in[14];
    const float* outb      = (const float*)d_in[15];
    float* out = (float*)d_out;

    void *pXc, *pIdx, *pGates, *pHc, *pEmb, *pGf, *pGb, *pLout, *pLog;
    cudaGetSymbolAddress(&pXc, g_Xc);
    cudaGetSymbolAddress(&pIdx, g_charidx);
    cudaGetSymbolAddress(&pGates, g_gates);
    cudaGetSymbolAddress(&pHc, g_Hc);
    cudaGetSymbolAddress(&pEmb, g_embeds);
    cudaGetSymbolAddress(&pGf, g_Gf);
    cudaGetSymbolAddress(&pGb, g_Gb);
    cudaGetSymbolAddress(&pLout, g_lstm_out);
    cudaGetSymbolAddress(&pLog, g_logits);

    /* allow 16-CTA (nonportable) clusters for the recurrent kernel */
    cudaFuncSetAttribute(recurrent_cluster,
                         cudaFuncAttributeNonPortableClusterSizeAllowed, 1);

    /* reset per-launch state (graph-replay determinism) */
    init_state<<<2048, 256>>>();

    /* char LSTM input projection for all (t,w): gather + GEMM */
    build_charidx<<<(LCC * S_LEN + 255) / 256, 256>>>(charsets);
    gemm_tn<<<dim3(4 * HC / 64, LCC * S_LEN / 64), 256>>>(
        char_emb, DC, cWih, cb, (float*)pXc,
        LCC * S_LEN, 4 * HC, DC, (const int*)pIdx, 0);

    /* char LSTM: 16 time steps, batched over S */
    for (int t = 0; t < LCC; t++) {
        gemm_tn<<<dim3(4 * HC / 64, S_LEN / 64), 256>>>(
            (const float*)pHc, HC, cWhh, nullptr, (float*)pGates,
            S_LEN, 4 * HC, HC, nullptr, 0);
        char_update<<<S_LEN * HC / 256, 256>>>(lengths, t);
    }

    /* embeds + main input projections */
    build_embeds<<<S_LEN * KIN / 256, 256>>>(sentence, word_emb);
    gemm_tn<<<dim3(4 * H2 / 64, S_LEN / 64), 256>>>(
        (const float*)pEmb, KIN, fWih, fb, (float*)pGf,
        S_LEN, 4 * H2, KIN, nullptr, 0);
    gemm_tn<<<dim3(4 * H2 / 64, S_LEN / 64), 256>>>(
        (const float*)pEmb, KIN, bWih, bb, (float*)pGb,
        S_LEN, 4 * H2, KIN, nullptr, 1);

    /* sequential bidirectional recurrence: 2 nonportable clusters of 16 */
    recurrent_cluster<<<2 * NBC, RT2>>>(fWhh, bWhh);

    /* output projection + log_softmax */
    gemm_tn<<<dim3(T_TAGS / 64, S_LEN / 64), 256>>>(
        (const float*)pLout, HH, outW, outb, (float*)pLog,
        S_LEN, T_TAGS, HH, nullptr, 0);
    logsoftmax_kernel<<<(S_LEN * 32 + 255) / 256, 256>>>(out);
}

// round 12
// speedup vs baseline: 2.3211x; 1.0250x over previous
#include <cuda_runtime.h>
#include <math.h>
#include <stdint.h>

#define S_LEN 8192
#define LCC   16
#define DW    256
#define DC    64
#define HC    128
#define HH    512
#define T_TAGS 64
#define H2    256
#define KIN   384      /* HC + DW */
#define NBC   16       /* CTAs per direction (nonportable cluster of 16) */
#define RT2   128      /* 4 warps per CTA; each warp owns 4 h-units */

/* ------------------- scratch (device globals; no allocation) ------------- */
__device__ float g_Xc[(size_t)LCC * S_LEN * 4 * HC];   /* permuted gate layout */
__device__ int   g_charidx[LCC * S_LEN];
__device__ float g_Hc2[2][S_LEN * HC];                 /* double-buffered char h */
__device__ float g_Cc[S_LEN * HC];
__device__ float g_charfeat[S_LEN * HC];
__device__ float g_Gf[(size_t)S_LEN * 4 * H2];
__device__ float g_Gb[(size_t)S_LEN * 4 * H2];
__device__ float g_lstm_out[S_LEN * HH];
__device__ float g_logits[S_LEN * T_TAGS];

/* fast gates: hardware MUFU tanh (sm_75+); sigmoid via tanh identity */
__device__ __forceinline__ float tanh_fast(float x) {
    float y;
    asm("tanh.approx.f32 %0, %1;" : "=f"(y) : "f"(x));
    return y;
}
__device__ __forceinline__ float sig_fast(float x) {
    return fmaf(tanh_fast(0.5f * x), 0.5f, 0.5f);
}

/* ---- PTX helpers ---- */
__device__ __forceinline__ uint32_t smem_u32(const void* p) {
    uint32_t a;
    asm("{ .reg .u64 t; cvta.to.shared.u64 t, %1; cvt.u32.u64 %0, t; }" : "=r"(a) : "l"(p));
    return a;
}
__device__ __forceinline__ uint32_t mapa_rank(uint32_t addr, uint32_t rank) {
    uint32_t r;
    asm("mapa.shared::cluster.u32 %0, %1, %2;" : "=r"(r) : "r"(addr), "r"(rank));
    return r;
}
__device__ __forceinline__ void mbar_wait_acq(uint32_t mbar, uint32_t parity) {
    uint32_t done;
    asm volatile(
        "{\n\t.reg .pred p;\n\t"
        "mbarrier.try_wait.parity.acquire.cluster.shared::cta.b64 p, [%1], %2;\n\t"
        "selp.b32 %0, 1, 0, p;\n\t}"
        : "=r"(done) : "r"(mbar), "r"(parity) : "memory");
    while (!done) {
        asm volatile(
            "{\n\t.reg .pred p;\n\t"
            "mbarrier.try_wait.parity.acquire.cluster.shared::cta.b64 p, [%1], %2, 0x989680;\n\t"
            "selp.b32 %0, 1, 0, p;\n\t}"
            : "=r"(done) : "r"(mbar), "r"(parity) : "memory");
    }
}
__device__ __forceinline__ void mbar_arm(uint32_t mbar, uint32_t tx) {
    asm volatile("mbarrier.arrive.expect_tx.shared::cta.b64 _, [%0], %1;"
                 :: "r"(mbar), "r"(tx) : "memory");
}
__device__ __forceinline__ void st_async_v2b64(uint32_t raddr, unsigned long long v0,
                                               unsigned long long v1, uint32_t rmbar) {
    asm volatile(
        "st.async.shared::cluster.mbarrier::complete_tx::bytes.v2.b64 [%0], {%1, %2}, [%3];"
        :: "r"(raddr), "l"(v0), "l"(v1), "r"(rmbar) : "memory");
}
#define FMA2(acc, a, b) asm("fma.rn.f32x2 %0, %1, %2, %0;" : "+l"(acc) : "l"(a), "l"(b))
#define UNPACK2(lo, hi, v) asm("mov.b64 {%0,%1}, %2;" : "=f"(lo), "=f"(hi) : "l"(v))

/* ------------------- init: must run every launch (graph determinism) ----- */
__global__ void init_state() {
    int idx = blockIdx.x * blockDim.x + threadIdx.x;
    int stride = gridDim.x * blockDim.x;
    for (int i = idx; i < S_LEN * HC; i += stride) {
        g_Hc2[0][i] = 0.0f;
        g_Cc[i] = 0.0f;
    }
}

__global__ void build_charidx(const int* __restrict__ charsets) {
    int idx = blockIdx.x * blockDim.x + threadIdx.x;
    if (idx >= LCC * S_LEN) return;
    int t = idx / S_LEN;
    int w = idx - t * S_LEN;
    g_charidx[idx] = charsets[w * LCC + t];
}

/* ------------------- generic fp32 GEMM (opt. permuted-gate B rows) --------
 * bperm: B row n maps to original row (n&3)*(N/4) + (n>>2); bias likewise.  */
__global__ void __launch_bounds__(256) gemm_tn(
    const float* __restrict__ A, int lda,
    const float* __restrict__ B,
    const float* __restrict__ bias,
    float* __restrict__ C, int M, int N, int K,
    const int* __restrict__ gidx, int rev, int bperm)
{
    __shared__ float4 As4[16 * 16];
    __shared__ float4 Bs4[16 * 16];
    float* As = (float*)As4;
    float* Bs = (float*)Bs4;

    int tid = threadIdx.x;
    int m0 = blockIdx.y * 64, n0 = blockIdx.x * 64;
    int lm = tid >> 2;
    int kq = tid & 3;

    int mg = m0 + lm;
    int arow = gidx ? gidx[mg] : (rev ? (M - 1 - mg) : mg);
    const float* Ap = A + (size_t)arow * lda;
    int brow = n0 + lm;
    int borig = bperm ? ((brow & 3) * (N >> 2) + (brow >> 2)) : brow;
    const float* Bp = B + (size_t)borig * K;

    int ty = tid >> 4, tx = tid & 15;
    float acc[4][4];
#pragma unroll
    for (int i = 0; i < 4; i++)
#pragma unroll
        for (int j = 0; j < 4; j++) acc[i][j] = 0.0f;

    for (int k0 = 0; k0 < K; k0 += 16) {
        float4 a = *(const float4*)(Ap + k0 + kq * 4);
        float4 b = *(const float4*)(Bp + k0 + kq * 4);
        __syncthreads();
        As[(kq * 4 + 0) * 64 + lm] = a.x;
        As[(kq * 4 + 1) * 64 + lm] = a.y;
        As[(kq * 4 + 2) * 64 + lm] = a.z;
        As[(kq * 4 + 3) * 64 + lm] = a.w;
        Bs[(kq * 4 + 0) * 64 + lm] = b.x;
        Bs[(kq * 4 + 1) * 64 + lm] = b.y;
        Bs[(kq * 4 + 2) * 64 + lm] = b.z;
        Bs[(kq * 4 + 3) * 64 + lm] = b.w;
        __syncthreads();
#pragma unroll
        for (int kk = 0; kk < 16; kk++) {
            float4 av = As4[kk * 16 + ty];
            float4 bv = Bs4[kk * 16 + tx];
            acc[0][0] += av.x * bv.x; acc[0][1] += av.x * bv.y;
            acc[0][2] += av.x * bv.z; acc[0][3] += av.x * bv.w;
            acc[1][0] += av.y * bv.x; acc[1][1] += av.y * bv.y;
            acc[1][2] += av.y * bv.z; acc[1][3] += av.y * bv.w;
            acc[2][0] += av.z * bv.x; acc[2][1] += av.z * bv.y;
            acc[2][2] += av.z * bv.z; acc[2][3] += av.z * bv.w;
            acc[3][0] += av.w * bv.x; acc[3][1] += av.w * bv.y;
            acc[3][2] += av.w * bv.z; acc[3][3] += av.w * bv.w;
        }
    }
#pragma unroll
    for (int i = 0; i < 4; i++) {
        int m = m0 + ty * 4 + i;
        int n = n0 + tx * 4;
        float4 o;
        o.x = acc[i][0]; o.y = acc[i][1]; o.z = acc[i][2]; o.w = acc[i][3];
        if (bias) {
            if (bperm) {
                int unit = (n0 >> 2) + tx;
                o.x += bias[0 * (N >> 2) + unit];
                o.y += bias[1 * (N >> 2) + unit];
                o.z += bias[2 * (N >> 2) + unit];
                o.w += bias[3 * (N >> 2) + unit];
            } else {
                o.x += bias[n + 0]; o.y += bias[n + 1];
                o.z += bias[n + 2]; o.w += bias[n + 3];
            }
        }
        *(float4*)(C + (size_t)m * N + n) = o;
    }
}

/* ------------------- fused char LSTM step: GEMM + gate epilogue -----------
 * A = HcR [8192,128]; B = cWhh with permuted gate rows; per-thread output
 * columns = one unit's {i,f,g,o}. Epilogue adds Xc (permuted, bias baked
 * in), does fast gate math, updates Cc in place and writes HcW/charfeat.
 * Hc double-buffered across launches (blocks read other blocks' rows).    */
__global__ void __launch_bounds__(256) char_step_fused(
    const float* __restrict__ HcR, const float* __restrict__ Whh,
    const float* __restrict__ Xct, float* __restrict__ Cc,
    float* __restrict__ HcW, float* __restrict__ charfeat,
    const int* __restrict__ lengths, int t)
{
    __shared__ float4 As4[16 * 16];
    __shared__ float4 Bs4[16 * 16];
    float* As = (float*)As4;
    float* Bs = (float*)Bs4;

    int tid = threadIdx.x;
    int m0 = blockIdx.y * 64, n0 = blockIdx.x * 64;
    int lm = tid >> 2;
    int kq = tid & 3;

    const float* Ap = HcR + (size_t)(m0 + lm) * HC;
    int brow = n0 + lm;
    int borig = (brow & 3) * HC + (brow >> 2);
    const float* Bp = Whh + (size_t)borig * HC;

    int ty = tid >> 4, tx = tid & 15;
    float acc[4][4];
#pragma unroll
    for (int i = 0; i < 4; i++)
#pragma unroll
        for (int j = 0; j < 4; j++) acc[i][j] = 0.0f;

    for (int k0 = 0; k0 < HC; k0 += 16) {
        float4 a = *(const float4*)(Ap + k0 + kq * 4);
        float4 b = *(const float4*)(Bp + k0 + kq * 4);
        __syncthreads();
        As[(kq * 4 + 0) * 64 + lm] = a.x;
        As[(kq * 4 + 1) * 64 + lm] = a.y;
        As[(kq * 4 + 2) * 64 + lm] = a.z;
        As[(kq * 4 + 3) * 64 + lm] = a.w;
        Bs[(kq * 4 + 0) * 64 + lm] = b.x;
        Bs[(kq * 4 + 1) * 64 + lm] = b.y;
        Bs[(kq * 4 + 2) * 64 + lm] = b.z;
        Bs[(kq * 4 + 3) * 64 + lm] = b.w;
        __syncthreads();
#pragma unroll
        for (int kk = 0; kk < 16; kk++) {
            float4 av = As4[kk * 16 + ty];
            float4 bv = Bs4[kk * 16 + tx];
            acc[0][0] += av.x * bv.x; acc[0][1] += av.x * bv.y;
            acc[0][2] += av.x * bv.z; acc[0][3] += av.x * bv.w;
            acc[1][0] += av.y * bv.x; acc[1][1] += av.y * bv.y;
            acc[1][2] += av.y * bv.z; acc[1][3] += av.y * bv.w;
            acc[2][0] += av.z * bv.x; acc[2][1] += av.z * bv.y;
            acc[2][2] += av.z * bv.z; acc[2][3] += av.z * bv.w;
            acc[3][0] += av.w * bv.x; acc[3][1] += av.w * bv.y;
            acc[3][2] += av.w * bv.z; acc[3][3] += av.w * bv.w;
        }
    }

    int unit = (n0 >> 2) + tx;
#pragma unroll
    for (int i = 0; i < 4; i++) {
        int m = m0 + ty * 4 + i;
        float4 x = *(const float4*)(Xct + (size_t)m * (4 * HC) + unit * 4);
        float gi = acc[i][0] + x.x;
        float gf = acc[i][1] + x.y;
        float gg = acc[i][2] + x.z;
        float go = acc[i][3] + x.w;
        float c = Cc[m * HC + unit];
        c = sig_fast(gf) * c + sig_fast(gi) * tanh_fast(gg);
        float h = sig_fast(go) * tanh_fast(c);
        Cc[m * HC + unit] = c;
        HcW[m * HC + unit] = h;
        if (t == lengths[m] - 1) charfeat[m * HC + unit] = h;
    }
}

/* ------------------- projection GEMM with fused embeds A-operand ----------
 * A row m, col k  =  k<HC ? charfeat[m][k] : word_emb[sentence[m]][k-HC].
 * rev reverses rows (backward direction). K = KIN = 384.                  */
__global__ void __launch_bounds__(256) gemm_emb(
    const int* __restrict__ sent,
    const float* __restrict__ cfeat,
    const float* __restrict__ wemb,
    const float* __restrict__ B,
    const float* __restrict__ bias,
    float* __restrict__ C, int M, int N, int rev)
{
    __shared__ float4 As4[16 * 16];
    __shared__ float4 Bs4[16 * 16];
    float* As = (float*)As4;
    float* Bs = (float*)Bs4;

    int tid = threadIdx.x;
    int m0 = blockIdx.y * 64, n0 = blockIdx.x * 64;
    int lm = tid >> 2;
    int kq = tid & 3;

    int mg = m0 + lm;
    int arow = rev ? (M - 1 - mg) : mg;
    int sidx = sent[arow];
    const float* cf = cfeat + (size_t)arow * HC;
    const float* we = wemb + (size_t)sidx * DW - HC;   /* index by col directly */
    const float* Bp = B + (size_t)(n0 + lm) * KIN;

    int ty = tid >> 4, tx = tid & 15;
    float acc[4][4];
#pragma unroll
    for (int i = 0; i < 4; i++)
#pragma unroll
        for (int j = 0; j < 4; j++) acc[i][j] = 0.0f;

    for (int k0 = 0; k0 < KIN; k0 += 16) {
        int col = k0 + kq * 4;
        float4 a = (col < HC) ? *(const float4*)(cf + col)
                              : *(const float4*)(we + col);
        float4 b = *(const float4*)(Bp + col);
        __syncthreads();
        As[(kq * 4 + 0) * 64 + lm] = a.x;
        As[(kq * 4 + 1) * 64 + lm] = a.y;
        As[(kq * 4 + 2) * 64 + lm] = a.z;
        As[(kq * 4 + 3) * 64 + lm] = a.w;
        Bs[(kq * 4 + 0) * 64 + lm] = b.x;
        Bs[(kq * 4 + 1) * 64 + lm] = b.y;
        Bs[(kq * 4 + 2) * 64 + lm] = b.z;
        Bs[(kq * 4 + 3) * 64 + lm] = b.w;
        __syncthreads();
#pragma unroll
        for (int kk = 0; kk < 16; kk++) {
            float4 av = As4[kk * 16 + ty];
            float4 bv = Bs4[kk * 16 + tx];
            acc[0][0] += av.x * bv.x; acc[0][1] += av.x * bv.y;
            acc[0][2] += av.x * bv.z; acc[0][3] += av.x * bv.w;
            acc[1][0] += av.y * bv.x; acc[1][1] += av.y * bv.y;
            acc[1][2] += av.y * bv.z; acc[1][3] += av.y * bv.w;
            acc[2][0] += av.z * bv.x; acc[2][1] += av.z * bv.y;
            acc[2][2] += av.z * bv.z; acc[2][3] += av.z * bv.w;
            acc[3][0] += av.w * bv.x; acc[3][1] += av.w * bv.y;
            acc[3][2] += av.w * bv.z; acc[3][3] += av.w * bv.w;
        }
    }
#pragma unroll
    for (int i = 0; i < 4; i++) {
        int m = m0 + ty * 4 + i;
        int n = n0 + tx * 4;
        float4 o;
        o.x = acc[i][0] + bias[n + 0];
        o.y = acc[i][1] + bias[n + 1];
        o.z = acc[i][2] + bias[n + 2];
        o.w = acc[i][3] + bias[n + 3];
        *(float4*)(C + (size_t)m * N + n) = o;
    }
}

/* ------------------- barrier-free cluster recurrence ----------------------
 * 2 nonportable clusters of 16 CTAs (one per direction), 128 threads =
 * 4 warps/CTA. Each WARP owns 4 h-units end-to-end. Lanes 0-3 each push
 * ONE 16-B st.async.v2.b64 to 4 of the 16 peer CTAs (parallel push).
 * Receiver: 64 tx events x 16 B per step, two alternating expect_tx(1024)
 * mbarriers re-armed by tid0 after wait. No syncthreads in the loop.      */
__global__ void __launch_bounds__(RT2, 1) __cluster_dims__(NBC, 1, 1)
recurrent_cluster(const float* __restrict__ WhhF, const float* __restrict__ WhhB)
{
    __shared__ __align__(16) float s_h[2][H2];
    __shared__ __align__(8) unsigned long long s_mbar[2];

    int tid = threadIdx.x;
    int wid = tid >> 5;
    int lane = tid & 31;
    int d = blockIdx.x >> 4;       /* cluster id = direction        */
    int b = blockIdx.x & 15;       /* rank within cluster           */
    const float* Whh = d ? WhhB : WhhF;
    const float* G = d ? g_Gb : g_Gf;

    int seg = lane & 1;            /* k half 0..1                    */
    int r_l = lane >> 1;           /* 0..15: ul = r_l>>2, gk = r_l&3 */
    int ul = r_l >> 2;
    int gk = r_l & 3;
    int u = b * 16 + wid * 4 + ul; /* global h-unit of this lane     */
    int row = gk * H2 + u;         /* gate row                       */

    /* 128 weights per lane, packed f32x2; k interleaved by float4(seg) */
    ulonglong2 w[32];
    const float* wrow = Whh + (size_t)row * H2;
#pragma unroll
    for (int jj = 0; jj < 32; jj++)
        w[jj] = *reinterpret_cast<const ulonglong2*>(wrow + (jj * 2 + seg) * 4);

    for (int i = tid; i < H2; i += RT2) { s_h[0][i] = 0.0f; s_h[1][i] = 0.0f; }

    uint32_t mb0 = smem_u32(&s_mbar[0]);
    uint32_t mb1 = smem_u32(&s_mbar[1]);
    if (tid == 0) {
        asm volatile("mbarrier.init.shared.b64 [%0], %1;" :: "r"(mb0), "r"(1) : "memory");
        asm volatile("mbarrier.init.shared.b64 [%0], %1;" :: "r"(mb1), "r"(1) : "memory");
        mbar_arm(mb0, 1024);   /* receives wave 1 */
        mbar_arm(mb1, 1024);   /* receives wave 0 */
        asm volatile("fence.mbarrier_init.release.cluster;" ::: "memory");
    }

    /* lanes 0..3 push to peers lane*4 .. lane*4+3 */
    uint32_t rh0[4], rh1[4], rm0[4], rm1[4];
    if (lane < 4) {
        uint32_t off = (uint32_t)(b * 16 + wid * 4) * 4u;
        uint32_t h0 = smem_u32(&s_h[0][0]) + off;
        uint32_t h1 = smem_u32(&s_h[1][0]) + off;
#pragma unroll
        for (int p = 0; p < 4; p++) {
            uint32_t peer = (uint32_t)(lane * 4 + p);
            rh0[p] = mapa_rank(h0, peer);
            rh1[p] = mapa_rank(h1, peer);
            rm0[p] = mapa_rank(mb0, peer);
            rm1[p] = mapa_rank(mb1, peer);
        }
    }

    __syncthreads();
    asm volatile("barrier.cluster.arrive.aligned;" ::: "memory");
    asm volatile("barrier.cluster.wait.aligned;" ::: "memory");

    uint32_t ph0 = 0, ph1 = 0;
    float c = 0.0f;
    float gin = 0.0f;
    if (seg == 0) gin = G[row];    /* prefetch t=0 */

    for (int t = 0; t < S_LEN; t++) {
        int idx = t & 1;
        if (t > 0) {
            uint32_t mb = idx ? mb1 : mb0;
            uint32_t ph = idx ? ph1 : ph0;
            mbar_wait_acq(mb, ph);
            if (idx) ph1 ^= 1; else ph0 ^= 1;
            if (tid == 0) mbar_arm(mb, 1024);   /* re-arm for wave t+2 */
        }

        const float* hb = s_h[idx];
        unsigned long long acc0 = 0ull, acc1 = 0ull;
#pragma unroll
        for (int jj = 0; jj < 32; jj++) {
            ulonglong2 hv = *reinterpret_cast<const ulonglong2*>(hb + (jj * 2 + seg) * 4);
            FMA2(acc0, w[jj].x, hv.x);
            FMA2(acc1, w[jj].y, hv.y);
        }
        float a0, a1, a2, a3;
        UNPACK2(a0, a1, acc0);
        UNPACK2(a2, a3, acc1);
        float acc = (a0 + a1) + (a2 + a3);
        acc += __shfl_xor_sync(0xffffffffu, acc, 1);   /* reduce k halves */
        if (seg == 0) acc += gin;                      /* +input proj     */

        /* gather this lane's unit gates (sources: even lanes) */
        int base = lane & 24;                          /* (lane>>3)*8     */
        float gi = __shfl_sync(0xffffffffu, acc, base + 0);
        float gf = __shfl_sync(0xffffffffu, acc, base + 2);
        float gg = __shfl_sync(0xffffffffu, acc, base + 4);
        float go = __shfl_sync(0xffffffffu, acc, base + 6);

        c = sig_fast(gf) * c + sig_fast(gi) * tanh_fast(gg);
        float h = sig_fast(go) * tanh_fast(c);

        if (seg == 0 && t + 1 < S_LEN)
            gin = G[(size_t)(t + 1) * (4 * H2) + row]; /* prefetch next   */

        if ((lane & 7) == 0) {                 /* lanes 0,8,16,24: 4 units */
            int outrow = d ? (S_LEN - 1 - t) : t;
            g_lstm_out[(size_t)outrow * HH + d * H2 + u] = h;
        }
        /* broadcast warp's 4 h values; lanes 0-3 push 4 peers each */
        float hB = __shfl_sync(0xffffffffu, h, 8);
        float hC = __shfl_sync(0xffffffffu, h, 16);
        float hD = __shfl_sync(0xffffffffu, h, 24);
        float hA = __shfl_sync(0xffffffffu, h, 0);

        if (lane < 4 && t + 1 < S_LEN) {
            unsigned long long p0, p1;
            asm("mov.b64 %0, {%1,%2};" : "=l"(p0) : "f"(hA), "f"(hB));
            asm("mov.b64 %0, {%1,%2};" : "=l"(p1) : "f"(hC), "f"(hD));
            if (idx) {          /* dst buffer 0, mbar 0 */
#pragma unroll
                for (int p = 0; p < 4; p++) st_async_v2b64(rh0[p], p0, p1, rm0[p]);
            } else {            /* dst buffer 1, mbar 1 */
#pragma unroll
                for (int p = 0; p < 4; p++) st_async_v2b64(rh1[p], p0, p1, rm1[p]);
            }
        }
    }

    asm volatile("barrier.cluster.arrive.aligned;" ::: "memory");
    asm volatile("barrier.cluster.wait.aligned;" ::: "memory");
}

/* ------------------- log_softmax over 64 tags (one warp per word) --------- */
__global__ void logsoftmax_kernel(float* __restrict__ out) {
    int gt = blockIdx.x * blockDim.x + threadIdx.x;
    int warp = gt >> 5;
    int lane = gt & 31;
    if (warp >= S_LEN) return;
    const float* l = g_logits + (size_t)warp * T_TAGS;
    float a = l[lane], b = l[lane + 32];
    float m = fmaxf(a, b);
#pragma unroll
    for (int o = 16; o > 0; o >>= 1) m = fmaxf(m, __shfl_xor_sync(0xffffffffu, m, o));
    float s = expf(a - m) + expf(b - m);
#pragma unroll
    for (int o = 16; o > 0; o >>= 1) s += __shfl_xor_sync(0xffffffffu, s, o);
    float lse = m + logf(s);
    out[(size_t)warp * T_TAGS + lane] = a - lse;
    out[(size_t)warp * T_TAGS + lane + 32] = b - lse;
}

/* ------------------- launcher --------------------------------------------- */
extern "C" void kernel_launch(void* const* d_in, const int* in_sizes, int n_in,
                              void* d_out, int out_size) {
    const int*   sentence  = (const int*)d_in[0];
    const int*   charsets  = (const int*)d_in[1];
    const int*   lengths   = (const int*)d_in[2];
    const float* word_emb  = (const float*)d_in[3];
    const float* char_emb  = (const float*)d_in[4];
    const float* cWih      = (const float*)d_in[5];
    const float* cWhh      = (const float*)d_in[6];
    const float* cb        = (const float*)d_in[7];
    const float* fWih      = (const float*)d_in[8];
    const float* fWhh      = (const float*)d_in[9];
    const float* fb        = (const float*)d_in[10];
    const float* bWih      = (const float*)d_in[11];
    const float* bWhh      = (const float*)d_in[12];
    const float* bb        = (const float*)d_in[13];
    const float* outW      = (const float*)d_in[14];
    const float* outb      = (const float*)d_in[15];
    float* out = (float*)d_out;

    void *pXc, *pIdx, *pHc2, *pCc, *pCf, *pGf, *pGb, *pLout, *pLog;
    cudaGetSymbolAddress(&pXc, g_Xc);
    cudaGetSymbolAddress(&pIdx, g_charidx);
    cudaGetSymbolAddress(&pHc2, g_Hc2);
    cudaGetSymbolAddress(&pCc, g_Cc);
    cudaGetSymbolAddress(&pCf, g_charfeat);
    cudaGetSymbolAddress(&pGf, g_Gf);
    cudaGetSymbolAddress(&pGb, g_Gb);
    cudaGetSymbolAddress(&pLout, g_lstm_out);
    cudaGetSymbolAddress(&pLog, g_logits);

    float* Hc0 = (float*)pHc2;
    float* Hc1 = Hc0 + (size_t)S_LEN * HC;

    /* allow 16-CTA (nonportable) clusters for the recurrent kernel */
    cudaFuncSetAttribute(recurrent_cluster,
                         cudaFuncAttributeNonPortableClusterSizeAllowed, 1);

    /* reset per-launch state (graph-replay determinism) */
    init_state<<<2048, 256>>>();

    /* char LSTM input projection for all (t,w): gather + GEMM (permuted) */
    build_charidx<<<(LCC * S_LEN + 255) / 256, 256>>>(charsets);
    gemm_tn<<<dim3(4 * HC / 64, LCC * S_LEN / 64), 256>>>(
        char_emb, DC, cWih, cb, (float*)pXc,
        LCC * S_LEN, 4 * HC, DC, (const int*)pIdx, 0, 1);

    /* char LSTM: 16 fused GEMM+gate steps, double-buffered h */
    for (int t = 0; t < LCC; t++) {
        const float* HcR = (t & 1) ? Hc1 : Hc0;
        float* HcW = (t & 1) ? Hc0 : Hc1;
        char_step_fused<<<dim3(8, 128), 256>>>(
            HcR, cWhh, (const float*)pXc + (size_t)t * S_LEN * 4 * HC,
            (float*)pCc, HcW, (float*)pCf, lengths, t);
    }

    /* main input projections with fused embeds gather */
    gemm_emb<<<dim3(4 * H2 / 64, S_LEN / 64), 256>>>(
        sentence, (const float*)pCf, word_emb, fWih, fb, (float*)pGf,
        S_LEN, 4 * H2, 0);
    gemm_emb<<<dim3(4 * H2 / 64, S_LEN / 64), 256>>>(
        sentence, (const float*)pCf, word_emb, bWih, bb, (float*)pGb,
        S_LEN, 4 * H2, 1);

    /* sequential bidirectional recurrence: 2 nonportable clusters of 16 */
    recurrent_cluster<<<2 * NBC, RT2>>>(fWhh, bWhh);

    /* output projection + log_softmax */
    gemm_tn<<<dim3(T_TAGS / 64, S_LEN / 64), 256>>>(
        (const float*)pLout, HH, outW, outb, (float*)pLog,
        S_LEN, T_TAGS, HH, nullptr, 0, 0);
    logsoftmax_kernel<<<(S_LEN * 32 + 255) / 256, 256>>>(out);
}

// round 13
// speedup vs baseline: 2.4535x; 1.0571x over previous
#include <cuda_runtime.h>
#include <math.h>
#include <stdint.h>

#define S_LEN 8192
#define LCC   16
#define DW    256
#define DC    64
#define HC    128
#define HH    512
#define CVV   128
#define T_TAGS 64
#define H2    256
#define KIN   384      /* HC + DW */
#define NBC   16       /* CTAs per direction (nonportable cluster of 16) */
#define RT2   128      /* 4 warps per CTA; each warp owns 4 h-units */

/* ------------------- scratch (device globals; no allocation) ------------- */
__device__ float g_XW[CVV * 4 * HC];                   /* per-char input proj (permuted) */
__device__ float g_Hc2[2][S_LEN * HC];                 /* double-buffered char h */
__device__ float g_Cc[S_LEN * HC];
__device__ float g_charfeat[S_LEN * HC];
__device__ float g_Gf[(size_t)S_LEN * 4 * H2];
__device__ float g_Gb[(size_t)S_LEN * 4 * H2];
__device__ float g_lstm_out[S_LEN * HH];
__device__ float g_logits[S_LEN * T_TAGS];

/* fast gates: hardware MUFU tanh (sm_75+); sigmoid via tanh identity */
__device__ __forceinline__ float tanh_fast(float x) {
    float y;
    asm("tanh.approx.f32 %0, %1;" : "=f"(y) : "f"(x));
    return y;
}
__device__ __forceinline__ float sig_fast(float x) {
    return fmaf(tanh_fast(0.5f * x), 0.5f, 0.5f);
}

/* ---- PTX helpers ---- */
__device__ __forceinline__ uint32_t smem_u32(const void* p) {
    uint32_t a;
    asm("{ .reg .u64 t; cvta.to.shared.u64 t, %1; cvt.u32.u64 %0, t; }" : "=r"(a) : "l"(p));
    return a;
}
__device__ __forceinline__ uint32_t mapa_rank(uint32_t addr, uint32_t rank) {
    uint32_t r;
    asm("mapa.shared::cluster.u32 %0, %1, %2;" : "=r"(r) : "r"(addr), "r"(rank));
    return r;
}
__device__ __forceinline__ void mbar_wait_acq(uint32_t mbar, uint32_t parity) {
    uint32_t done;
    asm volatile(
        "{\n\t.reg .pred p;\n\t"
        "mbarrier.try_wait.parity.acquire.cluster.shared::cta.b64 p, [%1], %2;\n\t"
        "selp.b32 %0, 1, 0, p;\n\t}"
        : "=r"(done) : "r"(mbar), "r"(parity) : "memory");
    while (!done) {
        asm volatile(
            "{\n\t.reg .pred p;\n\t"
            "mbarrier.try_wait.parity.acquire.cluster.shared::cta.b64 p, [%1], %2, 0x989680;\n\t"
            "selp.b32 %0, 1, 0, p;\n\t}"
            : "=r"(done) : "r"(mbar), "r"(parity) : "memory");
    }
}
__device__ __forceinline__ void mbar_arm(uint32_t mbar, uint32_t tx) {
    asm volatile("mbarrier.arrive.expect_tx.shared::cta.b64 _, [%0], %1;"
                 :: "r"(mbar), "r"(tx) : "memory");
}
__device__ __forceinline__ void st_async_v2b64(uint32_t raddr, unsigned long long v0,
                                               unsigned long long v1, uint32_t rmbar) {
    asm volatile(
        "st.async.shared::cluster.mbarrier::complete_tx::bytes.v2.b64 [%0], {%1, %2}, [%3];"
        :: "r"(raddr), "l"(v0), "l"(v1), "r"(rmbar) : "memory");
}
#define FMA2(acc, a, b) asm("fma.rn.f32x2 %0, %1, %2, %0;" : "+l"(acc) : "l"(a), "l"(b))
#define UNPACK2(lo, hi, v) asm("mov.b64 {%0,%1}, %2;" : "=f"(lo), "=f"(hi) : "l"(v))

/* ------------------- init: must run every launch (graph determinism) ----- */
__global__ void init_state() {
    int idx = blockIdx.x * blockDim.x + threadIdx.x;
    int stride = gridDim.x * blockDim.x;
    for (int i = idx; i < S_LEN * HC; i += stride) {
        g_Hc2[0][i] = 0.0f;
        g_Cc[i] = 0.0f;
    }
}

/* ------------------- per-char input projection table ----------------------
 * XW[c][n] = dot(char_emb[c], cWih[borig]) + cb[borig],
 * borig = (n&3)*HC + (n>>2) (gate-permuted so unit's {i,f,g,o} adjacent).  */
__global__ void build_xw(const float* __restrict__ ce,
                         const float* __restrict__ Wih,
                         const float* __restrict__ cb) {
    int idx = blockIdx.x * blockDim.x + threadIdx.x;
    if (idx >= CVV * 4 * HC) return;
    int c = idx >> 9;
    int n = idx & 511;
    int borig = (n & 3) * HC + (n >> 2);
    const float* w = Wih + (size_t)borig * DC;
    const float* e = ce + (size_t)c * DC;
    float s = cb[borig];
#pragma unroll
    for (int k = 0; k < DC; k++) s = fmaf(e[k], w[k], s);
    g_XW[idx] = s;
}

/* ------------------- generic fp32 GEMM ------------------------------------ */
__global__ void __launch_bounds__(256) gemm_tn(
    const float* __restrict__ A, int lda,
    const float* __restrict__ B,
    const float* __restrict__ bias,
    float* __restrict__ C, int M, int N, int K)
{
    __shared__ float4 As4[16 * 16];
    __shared__ float4 Bs4[16 * 16];
    float* As = (float*)As4;
    float* Bs = (float*)Bs4;

    int tid = threadIdx.x;
    int m0 = blockIdx.y * 64, n0 = blockIdx.x * 64;
    int lm = tid >> 2;
    int kq = tid & 3;

    const float* Ap = A + (size_t)(m0 + lm) * lda;
    const float* Bp = B + (size_t)(n0 + lm) * K;

    int ty = tid >> 4, tx = tid & 15;
    float acc[4][4];
#pragma unroll
    for (int i = 0; i < 4; i++)
#pragma unroll
        for (int j = 0; j < 4; j++) acc[i][j] = 0.0f;

    for (int k0 = 0; k0 < K; k0 += 16) {
        float4 a = *(const float4*)(Ap + k0 + kq * 4);
        float4 b = *(const float4*)(Bp + k0 + kq * 4);
        __syncthreads();
        As[(kq * 4 + 0) * 64 + lm] = a.x;
        As[(kq * 4 + 1) * 64 + lm] = a.y;
        As[(kq * 4 + 2) * 64 + lm] = a.z;
        As[(kq * 4 + 3) * 64 + lm] = a.w;
        Bs[(kq * 4 + 0) * 64 + lm] = b.x;
        Bs[(kq * 4 + 1) * 64 + lm] = b.y;
        Bs[(kq * 4 + 2) * 64 + lm] = b.z;
        Bs[(kq * 4 + 3) * 64 + lm] = b.w;
        __syncthreads();
#pragma unroll
        for (int kk = 0; kk < 16; kk++) {
            float4 av = As4[kk * 16 + ty];
            float4 bv = Bs4[kk * 16 + tx];
            acc[0][0] += av.x * bv.x; acc[0][1] += av.x * bv.y;
            acc[0][2] += av.x * bv.z; acc[0][3] += av.x * bv.w;
            acc[1][0] += av.y * bv.x; acc[1][1] += av.y * bv.y;
            acc[1][2] += av.y * bv.z; acc[1][3] += av.y * bv.w;
            acc[2][0] += av.z * bv.x; acc[2][1] += av.z * bv.y;
            acc[2][2] += av.z * bv.z; acc[2][3] += av.z * bv.w;
            acc[3][0] += av.w * bv.x; acc[3][1] += av.w * bv.y;
            acc[3][2] += av.w * bv.z; acc[3][3] += av.w * bv.w;
        }
    }
#pragma unroll
    for (int i = 0; i < 4; i++) {
        int m = m0 + ty * 4 + i;
        int n = n0 + tx * 4;
        float4 o;
        o.x = acc[i][0]; o.y = acc[i][1]; o.z = acc[i][2]; o.w = acc[i][3];
        if (bias) {
            o.x += bias[n + 0]; o.y += bias[n + 1];
            o.z += bias[n + 2]; o.w += bias[n + 3];
        }
        *(float4*)(C + (size_t)m * N + n) = o;
    }
}

/* ------------------- fused char LSTM step: GEMM + gate epilogue -----------
 * A = HcR [8192,128]; B = cWhh with permuted gate rows; per-thread output
 * columns = one unit's {i,f,g,o}. Epilogue gathers XW[charsets[m][t]]
 * (256-KB L2-resident table — replaces the 268-MB Xc tensor), does fast
 * gate math, updates Cc in place, writes HcW/charfeat.                    */
__global__ void __launch_bounds__(256) char_step_fused(
    const float* __restrict__ HcR, const float* __restrict__ Whh,
    const int* __restrict__ charsets, float* __restrict__ Cc,
    float* __restrict__ HcW, float* __restrict__ charfeat,
    const int* __restrict__ lengths, int t)
{
    __shared__ float4 As4[16 * 16];
    __shared__ float4 Bs4[16 * 16];
    float* As = (float*)As4;
    float* Bs = (float*)Bs4;

    int tid = threadIdx.x;
    int m0 = blockIdx.y * 64, n0 = blockIdx.x * 64;
    int lm = tid >> 2;
    int kq = tid & 3;

    const float* Ap = HcR + (size_t)(m0 + lm) * HC;
    int brow = n0 + lm;
    int borig = (brow & 3) * HC + (brow >> 2);
    const float* Bp = Whh + (size_t)borig * HC;

    int ty = tid >> 4, tx = tid & 15;
    float acc[4][4];
#pragma unroll
    for (int i = 0; i < 4; i++)
#pragma unroll
        for (int j = 0; j < 4; j++) acc[i][j] = 0.0f;

    for (int k0 = 0; k0 < HC; k0 += 16) {
        float4 a = *(const float4*)(Ap + k0 + kq * 4);
        float4 b = *(const float4*)(Bp + k0 + kq * 4);
        __syncthreads();
        As[(kq * 4 + 0) * 64 + lm] = a.x;
        As[(kq * 4 + 1) * 64 + lm] = a.y;
        As[(kq * 4 + 2) * 64 + lm] = a.z;
        As[(kq * 4 + 3) * 64 + lm] = a.w;
        Bs[(kq * 4 + 0) * 64 + lm] = b.x;
        Bs[(kq * 4 + 1) * 64 + lm] = b.y;
        Bs[(kq * 4 + 2) * 64 + lm] = b.z;
        Bs[(kq * 4 + 3) * 64 + lm] = b.w;
        __syncthreads();
#pragma unroll
        for (int kk = 0; kk < 16; kk++) {
            float4 av = As4[kk * 16 + ty];
            float4 bv = Bs4[kk * 16 + tx];
            acc[0][0] += av.x * bv.x; acc[0][1] += av.x * bv.y;
            acc[0][2] += av.x * bv.z; acc[0][3] += av.x * bv.w;
            acc[1][0] += av.y * bv.x; acc[1][1] += av.y * bv.y;
            acc[1][2] += av.y * bv.z; acc[1][3] += av.y * bv.w;
            acc[2][0] += av.z * bv.x; acc[2][1] += av.z * bv.y;
            acc[2][2] += av.z * bv.z; acc[2][3] += av.z * bv.w;
            acc[3][0] += av.w * bv.x; acc[3][1] += av.w * bv.y;
            acc[3][2] += av.w * bv.z; acc[3][3] += av.w * bv.w;
        }
    }

    int unit = (n0 >> 2) + tx;
#pragma unroll
    for (int i = 0; i < 4; i++) {
        int m = m0 + ty * 4 + i;
        int cidx = charsets[m * LCC + t];
        float4 x = *(const float4*)(g_XW + (size_t)cidx * (4 * HC) + unit * 4);
        float gi = acc[i][0] + x.x;
        float gf = acc[i][1] + x.y;
        float gg = acc[i][2] + x.z;
        float go = acc[i][3] + x.w;
        float c = Cc[m * HC + unit];
        c = sig_fast(gf) * c + sig_fast(gi) * tanh_fast(gg);
        float h = sig_fast(go) * tanh_fast(c);
        Cc[m * HC + unit] = c;
        HcW[m * HC + unit] = h;
        if (t == lengths[m] - 1) charfeat[m * HC + unit] = h;
    }
}

/* ------------------- projection GEMM with fused embeds A-operand ----------
 * A row m, col k  =  k<HC ? charfeat[m][k] : word_emb[sentence[m]][k-HC].
 * rev reverses rows (backward direction). K = KIN = 384.                  */
__global__ void __launch_bounds__(256) gemm_emb(
    const int* __restrict__ sent,
    const float* __restrict__ cfeat,
    const float* __restrict__ wemb,
    const float* __restrict__ B,
    const float* __restrict__ bias,
    float* __restrict__ C, int M, int N, int rev)
{
    __shared__ float4 As4[16 * 16];
    __shared__ float4 Bs4[16 * 16];
    float* As = (float*)As4;
    float* Bs = (float*)Bs4;

    int tid = threadIdx.x;
    int m0 = blockIdx.y * 64, n0 = blockIdx.x * 64;
    int lm = tid >> 2;
    int kq = tid & 3;

    int mg = m0 + lm;
    int arow = rev ? (M - 1 - mg) : mg;
    int sidx = sent[arow];
    const float* cf = cfeat + (size_t)arow * HC;
    const float* we = wemb + (size_t)sidx * DW - HC;   /* index by col directly */
    const float* Bp = B + (size_t)(n0 + lm) * KIN;

    int ty = tid >> 4, tx = tid & 15;
    float acc[4][4];
#pragma unroll
    for (int i = 0; i < 4; i++)
#pragma unroll
        for (int j = 0; j < 4; j++) acc[i][j] = 0.0f;

    for (int k0 = 0; k0 < KIN; k0 += 16) {
        int col = k0 + kq * 4;
        float4 a = (col < HC) ? *(const float4*)(cf + col)
                              : *(const float4*)(we + col);
        float4 b = *(const float4*)(Bp + col);
        __syncthreads();
        As[(kq * 4 + 0) * 64 + lm] = a.x;
        As[(kq * 4 + 1) * 64 + lm] = a.y;
        As[(kq * 4 + 2) * 64 + lm] = a.z;
        As[(kq * 4 + 3) * 64 + lm] = a.w;
        Bs[(kq * 4 + 0) * 64 + lm] = b.x;
        Bs[(kq * 4 + 1) * 64 + lm] = b.y;
        Bs[(kq * 4 + 2) * 64 + lm] = b.z;
        Bs[(kq * 4 + 3) * 64 + lm] = b.w;
        __syncthreads();
#pragma unroll
        for (int kk = 0; kk < 16; kk++) {
            float4 av = As4[kk * 16 + ty];
            float4 bv = Bs4[kk * 16 + tx];
            acc[0][0] += av.x * bv.x; acc[0][1] += av.x * bv.y;
            acc[0][2] += av.x * bv.z; acc[0][3] += av.x * bv.w;
            acc[1][0] += av.y * bv.x; acc[1][1] += av.y * bv.y;
            acc[1][2] += av.y * bv.z; acc[1][3] += av.y * bv.w;
            acc[2][0] += av.z * bv.x; acc[2][1] += av.z * bv.y;
            acc[2][2] += av.z * bv.z; acc[2][3] += av.z * bv.w;
            acc[3][0] += av.w * bv.x; acc[3][1] += av.w * bv.y;
            acc[3][2] += av.w * bv.z; acc[3][3] += av.w * bv.w;
        }
    }
#pragma unroll
    for (int i = 0; i < 4; i++) {
        int m = m0 + ty * 4 + i;
        int n = n0 + tx * 4;
        float4 o;
        o.x = acc[i][0] + bias[n + 0];
        o.y = acc[i][1] + bias[n + 1];
        o.z = acc[i][2] + bias[n + 2];
        o.w = acc[i][3] + bias[n + 3];
        *(float4*)(C + (size_t)m * N + n) = o;
    }
}

/* ------------------- barrier-free cluster recurrence ----------------------
 * 2 nonportable clusters of 16 CTAs (one per direction), 128 threads =
 * 4 warps/CTA. Each WARP owns 4 h-units end-to-end. Lanes 0-3 each push
 * ONE 16-B st.async.v2.b64 to 4 of the 16 peer CTAs (parallel push).
 * Receiver: 64 tx events x 16 B per step, two alternating expect_tx(1024)
 * mbarriers re-armed by tid0 after wait. No syncthreads in the loop.      */
__global__ void __launch_bounds__(RT2, 1) __cluster_dims__(NBC, 1, 1)
recurrent_cluster(const float* __restrict__ WhhF, const float* __restrict__ WhhB)
{
    __shared__ __align__(16) float s_h[2][H2];
    __shared__ __align__(8) unsigned long long s_mbar[2];

    int tid = threadIdx.x;
    int wid = tid >> 5;
    int lane = tid & 31;
    int d = blockIdx.x >> 4;       /* cluster id = direction        */
    int b = blockIdx.x & 15;       /* rank within cluster           */
    const float* Whh = d ? WhhB : WhhF;
    const float* G = d ? g_Gb : g_Gf;

    int seg = lane & 1;            /* k half 0..1                    */
    int r_l = lane >> 1;           /* 0..15: ul = r_l>>2, gk = r_l&3 */
    int ul = r_l >> 2;
    int gk = r_l & 3;
    int u = b * 16 + wid * 4 + ul; /* global h-unit of this lane     */
    int row = gk * H2 + u;         /* gate row                       */

    /* 128 weights per lane, packed f32x2; k interleaved by float4(seg) */
    ulonglong2 w[32];
    const float* wrow = Whh + (size_t)row * H2;
#pragma unroll
    for (int jj = 0; jj < 32; jj++)
        w[jj] = *reinterpret_cast<const ulonglong2*>(wrow + (jj * 2 + seg) * 4);

    for (int i = tid; i < H2; i += RT2) { s_h[0][i] = 0.0f; s_h[1][i] = 0.0f; }

    uint32_t mb0 = smem_u32(&s_mbar[0]);
    uint32_t mb1 = smem_u32(&s_mbar[1]);
    if (tid == 0) {
        asm volatile("mbarrier.init.shared.b64 [%0], %1;" :: "r"(mb0), "r"(1) : "memory");
        asm volatile("mbarrier.init.shared.b64 [%0], %1;" :: "r"(mb1), "r"(1) : "memory");
        mbar_arm(mb0, 1024);   /* receives wave 1 */
        mbar_arm(mb1, 1024);   /* receives wave 0 */
        asm volatile("fence.mbarrier_init.release.cluster;" ::: "memory");
    }

    /* lanes 0..3 push to peers lane*4 .. lane*4+3 */
    uint32_t rh0[4], rh1[4], rm0[4], rm1[4];
    if (lane < 4) {
        uint32_t off = (uint32_t)(b * 16 + wid * 4) * 4u;
        uint32_t h0 = smem_u32(&s_h[0][0]) + off;
        uint32_t h1 = smem_u32(&s_h[1][0]) + off;
#pragma unroll
        for (int p = 0; p < 4; p++) {
            uint32_t peer = (uint32_t)(lane * 4 + p);
            rh0[p] = mapa_rank(h0, peer);
            rh1[p] = mapa_rank(h1, peer);
            rm0[p] = mapa_rank(mb0, peer);
            rm1[p] = mapa_rank(mb1, peer);
        }
    }

    __syncthreads();
    asm volatile("barrier.cluster.arrive.aligned;" ::: "memory");
    asm volatile("barrier.cluster.wait.aligned;" ::: "memory");

    uint32_t ph0 = 0, ph1 = 0;
    float c = 0.0f;
    float gin = 0.0f;
    if (seg == 0) gin = G[row];    /* prefetch t=0 */

    for (int t = 0; t < S_LEN; t++) {
        int idx = t & 1;
        if (t > 0) {
            uint32_t mb = idx ? mb1 : mb0;
            uint32_t ph = idx ? ph1 : ph0;
            mbar_wait_acq(mb, ph);
            if (idx) ph1 ^= 1; else ph0 ^= 1;
            if (tid == 0) mbar_arm(mb, 1024);   /* re-arm for wave t+2 */
        }

        const float* hb = s_h[idx];
        unsigned long long acc0 = 0ull, acc1 = 0ull;
#pragma unroll
        for (int jj = 0; jj < 32; jj++) {
            ulonglong2 hv = *reinterpret_cast<const ulonglong2*>(hb + (jj * 2 + seg) * 4);
            FMA2(acc0, w[jj].x, hv.x);
            FMA2(acc1, w[jj].y, hv.y);
        }
        float a0, a1, a2, a3;
        UNPACK2(a0, a1, acc0);
        UNPACK2(a2, a3, acc1);
        float acc = (a0 + a1) + (a2 + a3);
        acc += __shfl_xor_sync(0xffffffffu, acc, 1);   /* reduce k halves */
        if (seg == 0) acc += gin;                      /* +input proj     */

        /* gather this lane's unit gates (sources: even lanes) */
        int base = lane & 24;                          /* (lane>>3)*8     */
        float gi = __shfl_sync(0xffffffffu, acc, base + 0);
        float gf = __shfl_sync(0xffffffffu, acc, base + 2);
        float gg = __shfl_sync(0xffffffffu, acc, base + 4);
        float go = __shfl_sync(0xffffffffu, acc, base + 6);

        c = sig_fast(gf) * c + sig_fast(gi) * tanh_fast(gg);
        float h = sig_fast(go) * tanh_fast(c);

        if (seg == 0 && t + 1 < S_LEN)
            gin = G[(size_t)(t + 1) * (4 * H2) + row]; /* prefetch next   */

        if ((lane & 7) == 0) {                 /* lanes 0,8,16,24: 4 units */
            int outrow = d ? (S_LEN - 1 - t) : t;
            g_lstm_out[(size_t)outrow * HH + d * H2 + u] = h;
        }
        /* broadcast warp's 4 h values; lanes 0-3 push 4 peers each */
        float hB = __shfl_sync(0xffffffffu, h, 8);
        float hC = __shfl_sync(0xffffffffu, h, 16);
        float hD = __shfl_sync(0xffffffffu, h, 24);
        float hA = __shfl_sync(0xffffffffu, h, 0);

        if (lane < 4 && t + 1 < S_LEN) {
            unsigned long long p0, p1;
            asm("mov.b64 %0, {%1,%2};" : "=l"(p0) : "f"(hA), "f"(hB));
            asm("mov.b64 %0, {%1,%2};" : "=l"(p1) : "f"(hC), "f"(hD));
            if (idx) {          /* dst buffer 0, mbar 0 */
#pragma unroll
                for (int p = 0; p < 4; p++) st_async_v2b64(rh0[p], p0, p1, rm0[p]);
            } else {            /* dst buffer 1, mbar 1 */
#pragma unroll
                for (int p = 0; p < 4; p++) st_async_v2b64(rh1[p], p0, p1, rm1[p]);
            }
        }
    }

    asm volatile("barrier.cluster.arrive.aligned;" ::: "memory");
    asm volatile("barrier.cluster.wait.aligned;" ::: "memory");
}

/* ------------------- log_softmax over 64 tags (one warp per word) --------- */
__global__ void logsoftmax_kernel(float* __restrict__ out) {
    int gt = blockIdx.x * blockDim.x + threadIdx.x;
    int warp = gt >> 5;
    int lane = gt & 31;
    if (warp >= S_LEN) return;
    const float* l = g_logits + (size_t)warp * T_TAGS;
    float a = l[lane], b = l[lane + 32];
    float m = fmaxf(a, b);
#pragma unroll
    for (int o = 16; o > 0; o >>= 1) m = fmaxf(m, __shfl_xor_sync(0xffffffffu, m, o));
    float s = expf(a - m) + expf(b - m);
#pragma unroll
    for (int o = 16; o > 0; o >>= 1) s += __shfl_xor_sync(0xffffffffu, s, o);
    float lse = m + logf(s);
    out[(size_t)warp * T_TAGS + lane] = a - lse;
    out[(size_t)warp * T_TAGS + lane + 32] = b - lse;
}

/* ------------------- launcher --------------------------------------------- */
extern "C" void kernel_launch(void* const* d_in, const int* in_sizes, int n_in,
                              void* d_out, int out_size) {
    const int*   sentence  = (const int*)d_in[0];
    const int*   charsets  = (const int*)d_in[1];
    const int*   lengths   = (const int*)d_in[2];
    const float* word_emb  = (const float*)d_in[3];
    const float* char_emb  = (const float*)d_in[4];
    const float* cWih      = (const float*)d_in[5];
    const float* cWhh      = (const float*)d_in[6];
    const float* cb        = (const float*)d_in[7];
    const float* fWih      = (const float*)d_in[8];
    const float* fWhh      = (const float*)d_in[9];
    const float* fb        = (const float*)d_in[10];
    const float* bWih      = (const float*)d_in[11];
    const float* bWhh      = (const float*)d_in[12];
    const float* bb        = (const float*)d_in[13];
    const float* outW      = (const float*)d_in[14];
    const float* outb      = (const float*)d_in[15];
    float* out = (float*)d_out;

    void *pHc2, *pCc, *pCf, *pGf, *pGb, *pLout, *pLog;
    cudaGetSymbolAddress(&pHc2, g_Hc2);
    cudaGetSymbolAddress(&pCc, g_Cc);
    cudaGetSymbolAddress(&pCf, g_charfeat);
    cudaGetSymbolAddress(&pGf, g_Gf);
    cudaGetSymbolAddress(&pGb, g_Gb);
    cudaGetSymbolAddress(&pLout, g_lstm_out);
    cudaGetSymbolAddress(&pLog, g_logits);

    float* Hc0 = (float*)pHc2;
    float* Hc1 = Hc0 + (size_t)S_LEN * HC;

    /* allow 16-CTA (nonportable) clusters for the recurrent kernel */
    cudaFuncSetAttribute(recurrent_cluster,
                         cudaFuncAttributeNonPortableClusterSizeAllowed, 1);

    /* reset per-launch state (graph-replay determinism) */
    init_state<<<2048, 256>>>();

    /* per-char input projection table: XW[128, 512] (gate-permuted + bias) */
    build_xw<<<(CVV * 4 * HC + 255) / 256, 256>>>(char_emb, cWih, cb);

    /* char LSTM: 16 fused GEMM+gate steps, double-buffered h, XW gather */
    for (int t = 0; t < LCC; t++) {
        const float* HcR = (t & 1) ? Hc1 : Hc0;
        float* HcW = (t & 1) ? Hc0 : Hc1;
        char_step_fused<<<dim3(8, 128), 256>>>(
            HcR, cWhh, charsets, (float*)pCc, HcW, (float*)pCf, lengths, t);
    }

    /* main input projections with fused embeds gather */
    gemm_emb<<<dim3(4 * H2 / 64, S_LEN / 64), 256>>>(
        sentence, (const float*)pCf, word_emb, fWih, fb, (float*)pGf,
        S_LEN, 4 * H2, 0);
    gemm_emb<<<dim3(4 * H2 / 64, S_LEN / 64), 256>>>(
        sentence, (const float*)pCf, word_emb, bWih, bb, (float*)pGb,
        S_LEN, 4 * H2, 1);

    /* sequential bidirectional recurrence: 2 nonportable clusters of 16 */
    recurrent_cluster<<<2 * NBC, RT2>>>(fWhh, bWhh);

    /* output projection + log_softmax */
    gemm_tn<<<dim3(T_TAGS / 64, S_LEN / 64), 256>>>(
        (const float*)pLout, HH, outW, outb, (float*)pLog,
        S_LEN, T_TAGS, HH);
    logsoftmax_kernel<<<(S_LEN * 32 + 255) / 256, 256>>>(out);
}